// round 3
// baseline (speedup 1.0000x reference)
#include <cuda_runtime.h>
#include <math.h>

// ---------------- problem constants ----------------
#define T_STEPS 16
#define BATCH   8192
#define HID     256
#define IN_F    64
#define OUT_F   64
#define NCLS    8
#define MROWS   (T_STEPS*BATCH)   // 131072
#define BH      (BATCH*HID)       // 2097152

// ---------------- output layout (reference return order, fp32) -------------
#define OFF_OUTSEQ 0
#define LEN_OUTSEQ (T_STEPS*BATCH*NCLS)          // 1,048,576
#define OFF_HC1    (OFF_OUTSEQ + LEN_OUTSEQ)     // 1,048,576
#define OFF_HC2    (OFF_HC1 + BH)                // 3,145,728
#define OFF_HC3    (OFF_HC2 + BH)                // 5,242,880
#define OFF_HC4    (OFF_HC3 + BH)                // 7,340,032
#define OFF_I2H    (OFF_HC4 + BH)                // 9,437,184
#define OFF_H2H    (OFF_I2H + (size_t)T_STEPS*BH) // 42,991,616
// total = 76,546,048 floats

// ---------------- scratch (__device__ globals: allocation-free) -------------
__device__ float g_hs[(size_t)MROWS * HID];      // hidden states, 134 MB
__device__ float g_out64[(size_t)MROWS * OUT_F]; // tanh(h @ W_h2o^T + b), 33.5 MB

// ---------------------------------------------------------------------------
// Generic register-blocked SGEMM:  C[m][n] = sum_k A[m][k] * Bm[n][k] (+epilogue)
//   A:  M x K row-major
//   Bm: N x K row-major (i.e. we compute A @ Bm^T)
// MODE 0: C = acc + bias[n]
// MODE 1: h2h = acc + bias[n]; C = h2h; h = tanh(add_in + h2h) -> h_out
//         (and fin_out if non-null)
// MODE 2: C = tanh(acc + bias[n])
// ---------------------------------------------------------------------------
template<int BM, int BN, int BK, int TM, int TN, int MODE>
__global__ void __launch_bounds__((BM/TM)*(BN/TN))
sgemm_kernel(int M, int N, int K,
             const float* __restrict__ A,
             const float* __restrict__ Bm,
             const float* __restrict__ bias,
             float* __restrict__ C,
             const float* __restrict__ add_in,
             float* __restrict__ h_out,
             float* __restrict__ fin_out)
{
    constexpr int THREADS = (BM/TM)*(BN/TN);
    __shared__ float As[BK][BM];
    __shared__ float Bs[BK][BN];

    const int tid = threadIdx.x;
    const int bm  = blockIdx.x * BM;
    const int bn  = blockIdx.y * BN;
    const int tncols = BN / TN;
    const int tn = (tid % tncols) * TN;
    const int tm = (tid / tncols) * TM;

    float acc[TM][TN];
#pragma unroll
    for (int i = 0; i < TM; i++)
#pragma unroll
        for (int j = 0; j < TN; j++) acc[i][j] = 0.0f;

    for (int k0 = 0; k0 < K; k0 += BK) {
        // stage A tile (BM x BK), transposed into As[k][m]
        for (int i = tid * 4; i < BM * BK; i += THREADS * 4) {
            int row = i / BK;
            int kk  = i % BK;               // multiple of 4 (BK is 8)
            const float4 v = *reinterpret_cast<const float4*>(
                &A[(size_t)(bm + row) * K + k0 + kk]);
            As[kk + 0][row] = v.x;
            As[kk + 1][row] = v.y;
            As[kk + 2][row] = v.z;
            As[kk + 3][row] = v.w;
        }
        // stage B tile (BN x BK), transposed into Bs[k][n]
        for (int i = tid * 4; i < BN * BK; i += THREADS * 4) {
            int row = i / BK;
            int kk  = i % BK;
            const float4 v = *reinterpret_cast<const float4*>(
                &Bm[(size_t)(bn + row) * K + k0 + kk]);
            Bs[kk + 0][row] = v.x;
            Bs[kk + 1][row] = v.y;
            Bs[kk + 2][row] = v.z;
            Bs[kk + 3][row] = v.w;
        }
        __syncthreads();

#pragma unroll
        for (int kk = 0; kk < BK; kk++) {
            float a[TM], b[TN];
#pragma unroll
            for (int i = 0; i < TM; i++) a[i] = As[kk][tm + i];
#pragma unroll
            for (int j = 0; j < TN; j++) b[j] = Bs[kk][tn + j];
#pragma unroll
            for (int i = 0; i < TM; i++)
#pragma unroll
                for (int j = 0; j < TN; j++)
                    acc[i][j] += a[i] * b[j];
        }
        __syncthreads();
    }

    // epilogue
#pragma unroll
    for (int i = 0; i < TM; i++) {
        const size_t m = (size_t)(bm + tm + i);
#pragma unroll
        for (int j = 0; j < TN; j++) {
            const int n = bn + tn + j;
            const float v = acc[i][j] + bias[n];
            const size_t idx = m * N + n;
            if (MODE == 0) {
                C[idx] = v;
            } else if (MODE == 1) {
                C[idx] = v;                            // h2h_seq[t]
                const float h = tanhf(add_in[idx] + v);
                h_out[idx] = h;                        // hs[t]
                if (fin_out) fin_out[idx] = h;         // hc1_final at t==15
            } else {
                C[idx] = tanhf(v);
            }
        }
    }
}

// ---------------------------------------------------------------------------
// Final classifier: out8[m][c] = sum_n out64[m][n] * W_fcc[c][n] + b_fcc[c]
// one row per thread
// ---------------------------------------------------------------------------
__global__ void __launch_bounds__(256)
fcc_kernel(const float* __restrict__ X, const float* __restrict__ W,
           const float* __restrict__ b, float* __restrict__ out)
{
    __shared__ float Ws[NCLS * OUT_F];
    __shared__ float bs[NCLS];
    const int tid = threadIdx.x;
    for (int i = tid; i < NCLS * OUT_F; i += blockDim.x) Ws[i] = W[i];
    if (tid < NCLS) bs[tid] = b[tid];
    __syncthreads();

    const size_t m = (size_t)blockIdx.x * blockDim.x + tid;
    const float* xr = X + m * OUT_F;

    float acc[NCLS];
#pragma unroll
    for (int c = 0; c < NCLS; c++) acc[c] = bs[c];

#pragma unroll
    for (int k = 0; k < OUT_F; k += 4) {
        const float4 v = *reinterpret_cast<const float4*>(xr + k);
#pragma unroll
        for (int c = 0; c < NCLS; c++) {
            acc[c] += v.x * Ws[c * OUT_F + k + 0];
            acc[c] += v.y * Ws[c * OUT_F + k + 1];
            acc[c] += v.z * Ws[c * OUT_F + k + 2];
            acc[c] += v.w * Ws[c * OUT_F + k + 3];
        }
    }
    float4* o = reinterpret_cast<float4*>(out + m * NCLS);
    o[0] = make_float4(acc[0], acc[1], acc[2], acc[3]);
    o[1] = make_float4(acc[4], acc[5], acc[6], acc[7]);
}

// ---------------------------------------------------------------------------
// Pass-through copies hc2, hc3, hc4 (float4 vectorized)
// ---------------------------------------------------------------------------
__global__ void __launch_bounds__(256)
copy3_kernel(const float4* __restrict__ a, const float4* __restrict__ b,
             const float4* __restrict__ c,
             float4* __restrict__ oa, float4* __restrict__ ob,
             float4* __restrict__ oc)
{
    const size_t i = (size_t)blockIdx.x * blockDim.x + threadIdx.x;
    oa[i] = a[i];
    ob[i] = b[i];
    oc[i] = c[i];
}

// ---------------------------------------------------------------------------
extern "C" void kernel_launch(void* const* d_in, const int* in_sizes, int n_in,
                              void* d_out, int out_size)
{
    const float* x      = (const float*)d_in[0];
    // d_in[1] = cue (unused by the reference computation)
    const float* hc1    = (const float*)d_in[2];
    const float* hc2    = (const float*)d_in[3];
    const float* hc3    = (const float*)d_in[4];
    const float* hc4    = (const float*)d_in[5];
    const float* W_i2h  = (const float*)d_in[6];
    const float* b_i2h  = (const float*)d_in[7];
    const float* W_h2h  = (const float*)d_in[8];
    const float* b_h2h  = (const float*)d_in[9];
    const float* W_h2o  = (const float*)d_in[10];
    const float* b_h2o  = (const float*)d_in[11];
    const float* W_fcc  = (const float*)d_in[12];
    const float* b_fcc  = (const float*)d_in[13];
    float* out = (float*)d_out;

    float *hs, *o64;
    cudaGetSymbolAddress((void**)&hs,  g_hs);
    cudaGetSymbolAddress((void**)&o64, g_out64);

    // hc2..hc4 pass-throughs (BH floats each -> BH/4 float4)
    copy3_kernel<<<(BH / 4) / 256, 256>>>(
        (const float4*)hc2, (const float4*)hc3, (const float4*)hc4,
        (float4*)(out + OFF_HC2), (float4*)(out + OFF_HC3),
        (float4*)(out + OFF_HC4));

    // i2h_seq = x @ W_i2h^T + b_i2h   [131072 x 256], K=64
    sgemm_kernel<128, 128, 8, 8, 8, 0><<<dim3(MROWS / 128, HID / 128), 256>>>(
        MROWS, HID, IN_F, x, W_i2h, b_i2h, out + OFF_I2H,
        nullptr, nullptr, nullptr);

    // sequential Elman recurrence: 16 dependent GEMMs [8192 x 256], K=256
    for (int t = 0; t < T_STEPS; t++) {
        const float* Ain = (t == 0) ? hc1 : hs + (size_t)(t - 1) * BH;
        sgemm_kernel<128, 128, 8, 8, 8, 1><<<dim3(BATCH / 128, HID / 128), 256>>>(
            BATCH, HID, HID, Ain, W_h2h, b_h2h,
            out + OFF_H2H + (size_t)t * BH,     // h2h_seq[t]
            out + OFF_I2H + (size_t)t * BH,     // i2h_seq[t] (input to tanh)
            hs + (size_t)t * BH,                // hs[t]
            (t == T_STEPS - 1) ? (out + OFF_HC1) : nullptr);
    }

    // out64 = tanh(hs @ W_h2o^T + b_h2o)   [131072 x 64], K=256
    sgemm_kernel<128, 64, 8, 8, 4, 2><<<dim3(MROWS / 128, OUT_F / 64), 256>>>(
        MROWS, OUT_F, HID, hs, W_h2o, b_h2o, o64,
        nullptr, nullptr, nullptr);

    // output_seq = out64 @ W_fcc^T + b_fcc   [131072 x 8]
    fcc_kernel<<<MROWS / 256, 256>>>(o64, W_fcc, b_fcc, out + OFF_OUTSEQ);
}

// round 5
// speedup vs baseline: 1.7342x; 1.7342x over previous
#include <cuda_runtime.h>
#include <math.h>

// ---------------- problem constants ----------------
#define T_STEPS 16
#define BATCH   8192
#define HID     256
#define IN_F    64
#define OUT_F   64
#define NCLS    8
#define MROWS   (T_STEPS*BATCH)   // 131072
#define BH      (BATCH*HID)       // 2097152

// ---------------- output layout (reference return order, fp32) -------------
#define OFF_OUTSEQ 0
#define LEN_OUTSEQ (T_STEPS*BATCH*NCLS)
#define OFF_HC1    (OFF_OUTSEQ + LEN_OUTSEQ)
#define OFF_HC2    (OFF_HC1 + BH)
#define OFF_HC3    (OFF_HC2 + BH)
#define OFF_HC4    (OFF_HC3 + BH)
#define OFF_I2H    (OFF_HC4 + BH)
#define OFF_H2H    (OFF_I2H + (size_t)T_STEPS*BH)

// ---------------- scratch (__device__ globals: allocation-free) -------------
__device__ float g_hs[(size_t)MROWS * HID];
__device__ float g_out64[(size_t)MROWS * OUT_F];

// ---------------- packed f32x2 helpers (sm_100+) ----------------------------
__device__ __forceinline__ unsigned long long pack2(float lo, float hi) {
    unsigned long long r;
    asm("mov.b64 %0, {%1, %2};" : "=l"(r) : "f"(lo), "f"(hi));
    return r;
}
__device__ __forceinline__ void unpack2(unsigned long long v, float& lo, float& hi) {
    asm("mov.b64 {%0, %1}, %2;" : "=f"(lo), "=f"(hi) : "l"(v));
}
__device__ __forceinline__ void ffma2(unsigned long long& d,
                                      unsigned long long a, unsigned long long b) {
    asm("fma.rn.f32x2 %0, %1, %2, %0;" : "+l"(d) : "l"(a), "l"(b));
}

// ---------------------------------------------------------------------------
// f32x2 register-blocked SGEMM:  C = A @ Bm^T + bias (+ optional tanh)
//   A:  M x K row-major,  Bm: N x K row-major
// Thread n-mapping: two float4 groups at tn0=(tid%(BN/8))*4 and tn1=tn0+BN/2
// (conflict-free LDS.128 of B pairs). MODE 0: linear. MODE 2: tanh.
// ---------------------------------------------------------------------------
template<int BM, int BN, int BK, int TM, int MODE>
__global__ void __launch_bounds__((BM/TM)*(BN/8))
sgemm2(int M, int N, int K,
       const float* __restrict__ A,
       const float* __restrict__ Bm,
       const float* __restrict__ bias,
       float* __restrict__ C)
{
    constexpr int THREADS = (BM/TM)*(BN/8);
    constexpr int NG = BN/8;                  // threads along n
    __shared__ float As[BK][BM];
    __shared__ float Bs[BK][BN];

    const int tid = threadIdx.x;
    const int bm  = blockIdx.x * BM;
    const int bn  = blockIdx.y * BN;
    const int tn0 = (tid % NG) * 4;
    const int tn1 = tn0 + BN/2;
    const int tm  = (tid / NG) * TM;

    unsigned long long acc[TM][4];
#pragma unroll
    for (int i = 0; i < TM; i++)
#pragma unroll
        for (int j = 0; j < 4; j++) acc[i][j] = 0ull;

    for (int k0 = 0; k0 < K; k0 += BK) {
        // stage A tile (BM x BK) transposed -> As[k][m]
        for (int i = tid * 4; i < BM * BK; i += THREADS * 4) {
            int row = i / BK, kk = i % BK;
            const float4 v = *reinterpret_cast<const float4*>(
                &A[(size_t)(bm + row) * K + k0 + kk]);
            As[kk+0][row] = v.x; As[kk+1][row] = v.y;
            As[kk+2][row] = v.z; As[kk+3][row] = v.w;
        }
        // stage B tile (BN x BK) transposed -> Bs[k][n]
        for (int i = tid * 4; i < BN * BK; i += THREADS * 4) {
            int row = i / BK, kk = i % BK;
            const float4 v = *reinterpret_cast<const float4*>(
                &Bm[(size_t)(bn + row) * K + k0 + kk]);
            Bs[kk+0][row] = v.x; Bs[kk+1][row] = v.y;
            Bs[kk+2][row] = v.z; Bs[kk+3][row] = v.w;
        }
        __syncthreads();

#pragma unroll
        for (int kk = 0; kk < BK; kk++) {
            const ulonglong2 b0 = *reinterpret_cast<const ulonglong2*>(&Bs[kk][tn0]);
            const ulonglong2 b1 = *reinterpret_cast<const ulonglong2*>(&Bs[kk][tn1]);
#pragma unroll
            for (int i = 0; i < TM; i++) {
                const float a = As[kk][tm + i];
                const unsigned long long a2 = pack2(a, a);
                ffma2(acc[i][0], a2, b0.x);
                ffma2(acc[i][1], a2, b0.y);
                ffma2(acc[i][2], a2, b1.x);
                ffma2(acc[i][3], a2, b1.y);
            }
        }
        __syncthreads();
    }

    const float4 bb0 = *reinterpret_cast<const float4*>(&bias[bn + tn0]);
    const float4 bb1 = *reinterpret_cast<const float4*>(&bias[bn + tn1]);
#pragma unroll
    for (int i = 0; i < TM; i++) {
        const size_t ro = (size_t)(bm + tm + i) * N + bn;
        float v0,v1,v2,v3,v4,v5,v6,v7;
        unpack2(acc[i][0], v0, v1); unpack2(acc[i][1], v2, v3);
        unpack2(acc[i][2], v4, v5); unpack2(acc[i][3], v6, v7);
        float4 r0 = make_float4(v0+bb0.x, v1+bb0.y, v2+bb0.z, v3+bb0.w);
        float4 r1 = make_float4(v4+bb1.x, v5+bb1.y, v6+bb1.z, v7+bb1.w);
        if (MODE == 2) {
            r0.x = tanhf(r0.x); r0.y = tanhf(r0.y); r0.z = tanhf(r0.z); r0.w = tanhf(r0.w);
            r1.x = tanhf(r1.x); r1.y = tanhf(r1.y); r1.z = tanhf(r1.z); r1.w = tanhf(r1.w);
        }
        *reinterpret_cast<float4*>(&C[ro + tn0]) = r0;
        *reinterpret_cast<float4*>(&C[ro + tn1]) = r1;
    }
}

// ---------------------------------------------------------------------------
// Persistent fused Elman recurrence: ONE launch for all 16 steps.
// Each block owns 64 batch rows; h kept resident in SMEM (transposed,
// padded stride HP=65 -> conflict-free broadcast a-loads + 4-way h-scatter).
// W_h2h (256 KB) streamed from L2 each step, double-buffered BK=8 tiles.
// ---------------------------------------------------------------------------
#define HP 65
__global__ void __launch_bounds__(256)
rnn_persist(const float* __restrict__ hc1, const float* __restrict__ W,
            const float* __restrict__ bias, const float* __restrict__ i2h,
            float* __restrict__ h2h_seq, float* __restrict__ hs_out,
            float* __restrict__ hc1_out)
{
    extern __shared__ float sm[];
    float* hT = sm;                                     // [HID][HP], m in [0,64)
    float (*Wb)[8][HID] = (float (*)[8][HID])(sm + HID*HP);  // [2][8][256]

    const int tid = threadIdx.x;
    const int bm  = blockIdx.x * 64;
    const int tn0 = (tid & 31) * 4;
    const int tn1 = tn0 + 128;
    const int tm  = (tid >> 5) * 8;

    // prologue: hc1 tile -> hT (transposed)
    for (int q = tid; q < 64 * (HID/4); q += 256) {
        const int m  = q >> 6;            // q / 64
        const int kq = (q & 63) * 4;
        const float4 v = *reinterpret_cast<const float4*>(
            &hc1[(size_t)(bm + m) * HID + kq]);
        hT[(kq+0)*HP + m] = v.x; hT[(kq+1)*HP + m] = v.y;
        hT[(kq+2)*HP + m] = v.z; hT[(kq+3)*HP + m] = v.w;
    }

    const float4 bb0 = *reinterpret_cast<const float4*>(&bias[tn0]);
    const float4 bb1 = *reinterpret_cast<const float4*>(&bias[tn1]);

    // per-thread W staging coords (2 float4 per 8x256 tile)
    const int n_0 = tid >> 1,        kk_0 = (tid & 1) * 4;
    const int n_1 = (256 + tid) >> 1, kk_1 = ((256 + tid) & 1) * 4;

#pragma unroll 1
    for (int t = 0; t < T_STEPS; t++) {
        // stage k-tile 0 into buffer 0
        {
            const float4 w0 = *reinterpret_cast<const float4*>(&W[(size_t)n_0*HID + kk_0]);
            const float4 w1 = *reinterpret_cast<const float4*>(&W[(size_t)n_1*HID + kk_1]);
            Wb[0][kk_0+0][n_0] = w0.x; Wb[0][kk_0+1][n_0] = w0.y;
            Wb[0][kk_0+2][n_0] = w0.z; Wb[0][kk_0+3][n_0] = w0.w;
            Wb[0][kk_1+0][n_1] = w1.x; Wb[0][kk_1+1][n_1] = w1.y;
            Wb[0][kk_1+2][n_1] = w1.z; Wb[0][kk_1+3][n_1] = w1.w;
        }
        __syncthreads();

        unsigned long long acc[8][4];
#pragma unroll
        for (int i = 0; i < 8; i++)
#pragma unroll
            for (int j = 0; j < 4; j++) acc[i][j] = 0ull;

#pragma unroll 1
        for (int kt = 0; kt < 32; kt++) {
            const int cur = kt & 1;
            float4 p0, p1;
            if (kt < 31) {  // prefetch next W tile (L2-hot after step 0)
                const int k0n = (kt + 1) * 8;
                p0 = *reinterpret_cast<const float4*>(&W[(size_t)n_0*HID + k0n + kk_0]);
                p1 = *reinterpret_cast<const float4*>(&W[(size_t)n_1*HID + k0n + kk_1]);
            }
            const float* ap = hT + (size_t)kt * 8 * HP + tm;
#pragma unroll
            for (int kk = 0; kk < 8; kk++) {
                const ulonglong2 b0 = *reinterpret_cast<const ulonglong2*>(&Wb[cur][kk][tn0]);
                const ulonglong2 b1 = *reinterpret_cast<const ulonglong2*>(&Wb[cur][kk][tn1]);
#pragma unroll
                for (int i = 0; i < 8; i++) {
                    const float a = ap[kk*HP + i];
                    const unsigned long long a2 = pack2(a, a);
                    ffma2(acc[i][0], a2, b0.x);
                    ffma2(acc[i][1], a2, b0.y);
                    ffma2(acc[i][2], a2, b1.x);
                    ffma2(acc[i][3], a2, b1.y);
                }
            }
            if (kt < 31) {
                const int nb = 1 - cur;
                Wb[nb][kk_0+0][n_0] = p0.x; Wb[nb][kk_0+1][n_0] = p0.y;
                Wb[nb][kk_0+2][n_0] = p0.z; Wb[nb][kk_0+3][n_0] = p0.w;
                Wb[nb][kk_1+0][n_1] = p1.x; Wb[nb][kk_1+1][n_1] = p1.y;
                Wb[nb][kk_1+2][n_1] = p1.z; Wb[nb][kk_1+3][n_1] = p1.w;
                __syncthreads();
            }
        }
        __syncthreads();   // all hT reads of this step complete

        // epilogue: h2h -> out, h = tanh(i2h + h2h) -> hs_out + resident hT
        const size_t base = ((size_t)t * BATCH + bm + tm) * HID;
#pragma unroll
        for (int i = 0; i < 8; i++) {
            const size_t ro = base + (size_t)i * HID;
            float v0,v1,v2,v3,v4,v5,v6,v7;
            unpack2(acc[i][0], v0, v1); unpack2(acc[i][1], v2, v3);
            unpack2(acc[i][2], v4, v5); unpack2(acc[i][3], v6, v7);
            const float4 h0 = make_float4(v0+bb0.x, v1+bb0.y, v2+bb0.z, v3+bb0.w);
            const float4 h1 = make_float4(v4+bb1.x, v5+bb1.y, v6+bb1.z, v7+bb1.w);
            *reinterpret_cast<float4*>(&h2h_seq[ro + tn0]) = h0;
            *reinterpret_cast<float4*>(&h2h_seq[ro + tn1]) = h1;
            const float4 x0 = *reinterpret_cast<const float4*>(&i2h[ro + tn0]);
            const float4 x1 = *reinterpret_cast<const float4*>(&i2h[ro + tn1]);
            const float4 n0v = make_float4(tanhf(x0.x+h0.x), tanhf(x0.y+h0.y),
                                           tanhf(x0.z+h0.z), tanhf(x0.w+h0.w));
            const float4 n1v = make_float4(tanhf(x1.x+h1.x), tanhf(x1.y+h1.y),
                                           tanhf(x1.z+h1.z), tanhf(x1.w+h1.w));
            *reinterpret_cast<float4*>(&hs_out[ro + tn0]) = n0v;
            *reinterpret_cast<float4*>(&hs_out[ro + tn1]) = n1v;
            if (t == T_STEPS - 1) {
                const size_t rh = (size_t)(bm + tm + i) * HID;
                *reinterpret_cast<float4*>(&hc1_out[rh + tn0]) = n0v;
                *reinterpret_cast<float4*>(&hc1_out[rh + tn1]) = n1v;
            }
            const int mi = tm + i;
            hT[(tn0+0)*HP + mi] = n0v.x; hT[(tn0+1)*HP + mi] = n0v.y;
            hT[(tn0+2)*HP + mi] = n0v.z; hT[(tn0+3)*HP + mi] = n0v.w;
            hT[(tn1+0)*HP + mi] = n1v.x; hT[(tn1+1)*HP + mi] = n1v.y;
            hT[(tn1+2)*HP + mi] = n1v.z; hT[(tn1+3)*HP + mi] = n1v.w;
        }
        __syncthreads();   // hT updated before next step reads it
    }
}

// ---------------------------------------------------------------------------
__global__ void __launch_bounds__(256)
fcc_kernel(const float* __restrict__ X, const float* __restrict__ W,
           const float* __restrict__ b, float* __restrict__ out)
{
    __shared__ float Ws[NCLS * OUT_F];
    __shared__ float bs[NCLS];
    const int tid = threadIdx.x;
    for (int i = tid; i < NCLS * OUT_F; i += blockDim.x) Ws[i] = W[i];
    if (tid < NCLS) bs[tid] = b[tid];
    __syncthreads();

    const size_t m = (size_t)blockIdx.x * blockDim.x + tid;
    const float* xr = X + m * OUT_F;

    float acc[NCLS];
#pragma unroll
    for (int c = 0; c < NCLS; c++) acc[c] = bs[c];
#pragma unroll
    for (int k = 0; k < OUT_F; k += 4) {
        const float4 v = *reinterpret_cast<const float4*>(xr + k);
#pragma unroll
        for (int c = 0; c < NCLS; c++) {
            acc[c] += v.x * Ws[c*OUT_F + k+0];
            acc[c] += v.y * Ws[c*OUT_F + k+1];
            acc[c] += v.z * Ws[c*OUT_F + k+2];
            acc[c] += v.w * Ws[c*OUT_F + k+3];
        }
    }
    float4* o = reinterpret_cast<float4*>(out + m * NCLS);
    o[0] = make_float4(acc[0], acc[1], acc[2], acc[3]);
    o[1] = make_float4(acc[4], acc[5], acc[6], acc[7]);
}

__global__ void __launch_bounds__(256)
copy3_kernel(const float4* __restrict__ a, const float4* __restrict__ b,
             const float4* __restrict__ c,
             float4* __restrict__ oa, float4* __restrict__ ob,
             float4* __restrict__ oc)
{
    const size_t i = (size_t)blockIdx.x * blockDim.x + threadIdx.x;
    oa[i] = a[i]; ob[i] = b[i]; oc[i] = c[i];
}

// ---------------------------------------------------------------------------
extern "C" void kernel_launch(void* const* d_in, const int* in_sizes, int n_in,
                              void* d_out, int out_size)
{
    const float* x      = (const float*)d_in[0];
    const float* hc1    = (const float*)d_in[2];
    const float* hc2    = (const float*)d_in[3];
    const float* hc3    = (const float*)d_in[4];
    const float* hc4    = (const float*)d_in[5];
    const float* W_i2h  = (const float*)d_in[6];
    const float* b_i2h  = (const float*)d_in[7];
    const float* W_h2h  = (const float*)d_in[8];
    const float* b_h2h  = (const float*)d_in[9];
    const float* W_h2o  = (const float*)d_in[10];
    const float* b_h2o  = (const float*)d_in[11];
    const float* W_fcc  = (const float*)d_in[12];
    const float* b_fcc  = (const float*)d_in[13];
    float* out = (float*)d_out;

    float *hs, *o64;
    cudaGetSymbolAddress((void**)&hs,  g_hs);
    cudaGetSymbolAddress((void**)&o64, g_out64);

    // pass-throughs
    copy3_kernel<<<(BH/4)/256, 256>>>(
        (const float4*)hc2, (const float4*)hc3, (const float4*)hc4,
        (float4*)(out + OFF_HC2), (float4*)(out + OFF_HC3), (float4*)(out + OFF_HC4));

    // i2h_seq = x @ W_i2h^T + b  [131072 x 256], K=64
    sgemm2<128, 128, 8, 8, 0><<<dim3(MROWS/128, HID/128), 256>>>(
        MROWS, HID, IN_F, x, W_i2h, b_i2h, out + OFF_I2H);

    // persistent fused 16-step recurrence
    const int smem_bytes = (HID*HP + 2*8*HID) * (int)sizeof(float);  // 82,944 B
    cudaFuncSetAttribute(rnn_persist,
                         cudaFuncAttributeMaxDynamicSharedMemorySize, smem_bytes);
    rnn_persist<<<BATCH/64, 256, smem_bytes>>>(
        hc1, W_h2h, b_h2h, out + OFF_I2H,
        out + OFF_H2H, hs, out + OFF_HC1);

    // out64 = tanh(hs @ W_h2o^T + b)  [131072 x 64], K=256
    sgemm2<128, 64, 8, 8, 2><<<dim3(MROWS/128, 1), 128>>>(
        MROWS, OUT_F, HID, hs, W_h2o, b_h2o, o64);

    // output_seq = out64 @ W_fcc^T + b_fcc
    fcc_kernel<<<MROWS/256, 256>>>(o64, W_fcc, b_fcc, out + OFF_OUTSEQ);
}

// round 7
// speedup vs baseline: 1.7347x; 1.0003x over previous
#include <cuda_runtime.h>
#include <math.h>

// ---------------- problem constants ----------------
#define T_STEPS 16
#define BATCH   8192
#define HID     256
#define IN_F    64
#define OUT_F   64
#define NCLS    8
#define MROWS   (T_STEPS*BATCH)   // 131072
#define BH      (BATCH*HID)       // 2097152

// ---------------- output layout (reference return order, fp32) -------------
#define OFF_OUTSEQ 0
#define LEN_OUTSEQ (T_STEPS*BATCH*NCLS)
#define OFF_HC1    (OFF_OUTSEQ + LEN_OUTSEQ)
#define OFF_HC2    (OFF_HC1 + BH)
#define OFF_HC3    (OFF_HC2 + BH)
#define OFF_HC4    (OFF_HC3 + BH)
#define OFF_I2H    (OFF_HC4 + BH)
#define OFF_H2H    (OFF_I2H + (size_t)T_STEPS*BH)

// ---------------- scratch (__device__ globals: allocation-free) -------------
__device__ float g_hs[(size_t)MROWS * HID];
__device__ float g_out64[(size_t)MROWS * OUT_F];

// ---------------- packed f32x2 helpers (sm_100+) ----------------------------
__device__ __forceinline__ unsigned long long pack2(float lo, float hi) {
    unsigned long long r;
    asm("mov.b64 %0, {%1, %2};" : "=l"(r) : "f"(lo), "f"(hi));
    return r;
}
__device__ __forceinline__ void unpack2(unsigned long long v, float& lo, float& hi) {
    asm("mov.b64 {%0, %1}, %2;" : "=f"(lo), "=f"(hi) : "l"(v));
}
__device__ __forceinline__ void ffma2(unsigned long long& d,
                                      unsigned long long a, unsigned long long b) {
    asm("fma.rn.f32x2 %0, %1, %2, %0;" : "+l"(d) : "l"(a), "l"(b));
}

// ---------------------------------------------------------------------------
// f32x2 register-blocked SGEMM:  C = A @ Bm^T + bias (+ optional tanh)
//   A:  M x K row-major,  Bm: N x K row-major
// Thread n-mapping: two float4 groups at tn0=(tid%(BN/8))*4 and tn1=tn0+BN/2
// (conflict-free LDS.128 of B pairs). MODE 0: linear. MODE 2: tanh.
// ---------------------------------------------------------------------------
template<int BM, int BN, int BK, int TM, int MODE>
__global__ void __launch_bounds__((BM/TM)*(BN/8))
sgemm2(int M, int N, int K,
       const float* __restrict__ A,
       const float* __restrict__ Bm,
       const float* __restrict__ bias,
       float* __restrict__ C)
{
    constexpr int THREADS = (BM/TM)*(BN/8);
    constexpr int NG = BN/8;                  // threads along n
    __shared__ float As[BK][BM];
    __shared__ float Bs[BK][BN];

    const int tid = threadIdx.x;
    const int bm  = blockIdx.x * BM;
    const int bn  = blockIdx.y * BN;
    const int tn0 = (tid % NG) * 4;
    const int tn1 = tn0 + BN/2;
    const int tm  = (tid / NG) * TM;

    unsigned long long acc[TM][4];
#pragma unroll
    for (int i = 0; i < TM; i++)
#pragma unroll
        for (int j = 0; j < 4; j++) acc[i][j] = 0ull;

    for (int k0 = 0; k0 < K; k0 += BK) {
        // stage A tile (BM x BK) transposed -> As[k][m]
        for (int i = tid * 4; i < BM * BK; i += THREADS * 4) {
            int row = i / BK, kk = i % BK;
            const float4 v = *reinterpret_cast<const float4*>(
                &A[(size_t)(bm + row) * K + k0 + kk]);
            As[kk+0][row] = v.x; As[kk+1][row] = v.y;
            As[kk+2][row] = v.z; As[kk+3][row] = v.w;
        }
        // stage B tile (BN x BK) transposed -> Bs[k][n]
        for (int i = tid * 4; i < BN * BK; i += THREADS * 4) {
            int row = i / BK, kk = i % BK;
            const float4 v = *reinterpret_cast<const float4*>(
                &Bm[(size_t)(bn + row) * K + k0 + kk]);
            Bs[kk+0][row] = v.x; Bs[kk+1][row] = v.y;
            Bs[kk+2][row] = v.z; Bs[kk+3][row] = v.w;
        }
        __syncthreads();

#pragma unroll
        for (int kk = 0; kk < BK; kk++) {
            const ulonglong2 b0 = *reinterpret_cast<const ulonglong2*>(&Bs[kk][tn0]);
            const ulonglong2 b1 = *reinterpret_cast<const ulonglong2*>(&Bs[kk][tn1]);
#pragma unroll
            for (int i = 0; i < TM; i++) {
                const float a = As[kk][tm + i];
                const unsigned long long a2 = pack2(a, a);
                ffma2(acc[i][0], a2, b0.x);
                ffma2(acc[i][1], a2, b0.y);
                ffma2(acc[i][2], a2, b1.x);
                ffma2(acc[i][3], a2, b1.y);
            }
        }
        __syncthreads();
    }

    const float4 bb0 = *reinterpret_cast<const float4*>(&bias[bn + tn0]);
    const float4 bb1 = *reinterpret_cast<const float4*>(&bias[bn + tn1]);
#pragma unroll
    for (int i = 0; i < TM; i++) {
        const size_t ro = (size_t)(bm + tm + i) * N + bn;
        float v0,v1,v2,v3,v4,v5,v6,v7;
        unpack2(acc[i][0], v0, v1); unpack2(acc[i][1], v2, v3);
        unpack2(acc[i][2], v4, v5); unpack2(acc[i][3], v6, v7);
        float4 r0 = make_float4(v0+bb0.x, v1+bb0.y, v2+bb0.z, v3+bb0.w);
        float4 r1 = make_float4(v4+bb1.x, v5+bb1.y, v6+bb1.z, v7+bb1.w);
        if (MODE == 2) {
            r0.x = tanhf(r0.x); r0.y = tanhf(r0.y); r0.z = tanhf(r0.z); r0.w = tanhf(r0.w);
            r1.x = tanhf(r1.x); r1.y = tanhf(r1.y); r1.z = tanhf(r1.z); r1.w = tanhf(r1.w);
        }
        *reinterpret_cast<float4*>(&C[ro + tn0]) = r0;
        *reinterpret_cast<float4*>(&C[ro + tn1]) = r1;
    }
}

// ---------------------------------------------------------------------------
// Persistent fused Elman recurrence: ONE launch for all 16 steps.
// Each block owns 64 batch rows; h kept resident in SMEM (transposed,
// padded stride HP=65 -> conflict-free broadcast a-loads + 4-way h-scatter).
// W_h2h (256 KB) streamed from L2 each step, double-buffered BK=8 tiles.
// ---------------------------------------------------------------------------
#define HP 65
__global__ void __launch_bounds__(256)
rnn_persist(const float* __restrict__ hc1, const float* __restrict__ W,
            const float* __restrict__ bias, const float* __restrict__ i2h,
            float* __restrict__ h2h_seq, float* __restrict__ hs_out,
            float* __restrict__ hc1_out)
{
    extern __shared__ float sm[];
    float* hT = sm;                                     // [HID][HP], m in [0,64)
    float (*Wb)[8][HID] = (float (*)[8][HID])(sm + HID*HP);  // [2][8][256]

    const int tid = threadIdx.x;
    const int bm  = blockIdx.x * 64;
    const int tn0 = (tid & 31) * 4;
    const int tn1 = tn0 + 128;
    const int tm  = (tid >> 5) * 8;

    // prologue: hc1 tile -> hT (transposed)
    for (int q = tid; q < 64 * (HID/4); q += 256) {
        const int m  = q >> 6;            // q / 64
        const int kq = (q & 63) * 4;
        const float4 v = *reinterpret_cast<const float4*>(
            &hc1[(size_t)(bm + m) * HID + kq]);
        hT[(kq+0)*HP + m] = v.x; hT[(kq+1)*HP + m] = v.y;
        hT[(kq+2)*HP + m] = v.z; hT[(kq+3)*HP + m] = v.w;
    }

    const float4 bb0 = *reinterpret_cast<const float4*>(&bias[tn0]);
    const float4 bb1 = *reinterpret_cast<const float4*>(&bias[tn1]);

    // per-thread W staging coords (2 float4 per 8x256 tile)
    const int n_0 = tid >> 1,        kk_0 = (tid & 1) * 4;
    const int n_1 = (256 + tid) >> 1, kk_1 = ((256 + tid) & 1) * 4;

#pragma unroll 1
    for (int t = 0; t < T_STEPS; t++) {
        // stage k-tile 0 into buffer 0
        {
            const float4 w0 = *reinterpret_cast<const float4*>(&W[(size_t)n_0*HID + kk_0]);
            const float4 w1 = *reinterpret_cast<const float4*>(&W[(size_t)n_1*HID + kk_1]);
            Wb[0][kk_0+0][n_0] = w0.x; Wb[0][kk_0+1][n_0] = w0.y;
            Wb[0][kk_0+2][n_0] = w0.z; Wb[0][kk_0+3][n_0] = w0.w;
            Wb[0][kk_1+0][n_1] = w1.x; Wb[0][kk_1+1][n_1] = w1.y;
            Wb[0][kk_1+2][n_1] = w1.z; Wb[0][kk_1+3][n_1] = w1.w;
        }
        __syncthreads();

        unsigned long long acc[8][4];
#pragma unroll
        for (int i = 0; i < 8; i++)
#pragma unroll
            for (int j = 0; j < 4; j++) acc[i][j] = 0ull;

#pragma unroll 1
        for (int kt = 0; kt < 32; kt++) {
            const int cur = kt & 1;
            float4 p0, p1;
            if (kt < 31) {  // prefetch next W tile (L2-hot after step 0)
                const int k0n = (kt + 1) * 8;
                p0 = *reinterpret_cast<const float4*>(&W[(size_t)n_0*HID + k0n + kk_0]);
                p1 = *reinterpret_cast<const float4*>(&W[(size_t)n_1*HID + k0n + kk_1]);
            }
            const float* ap = hT + (size_t)kt * 8 * HP + tm;
#pragma unroll
            for (int kk = 0; kk < 8; kk++) {
                const ulonglong2 b0 = *reinterpret_cast<const ulonglong2*>(&Wb[cur][kk][tn0]);
                const ulonglong2 b1 = *reinterpret_cast<const ulonglong2*>(&Wb[cur][kk][tn1]);
#pragma unroll
                for (int i = 0; i < 8; i++) {
                    const float a = ap[kk*HP + i];
                    const unsigned long long a2 = pack2(a, a);
                    ffma2(acc[i][0], a2, b0.x);
                    ffma2(acc[i][1], a2, b0.y);
                    ffma2(acc[i][2], a2, b1.x);
                    ffma2(acc[i][3], a2, b1.y);
                }
            }
            if (kt < 31) {
                const int nb = 1 - cur;
                Wb[nb][kk_0+0][n_0] = p0.x; Wb[nb][kk_0+1][n_0] = p0.y;
                Wb[nb][kk_0+2][n_0] = p0.z; Wb[nb][kk_0+3][n_0] = p0.w;
                Wb[nb][kk_1+0][n_1] = p1.x; Wb[nb][kk_1+1][n_1] = p1.y;
                Wb[nb][kk_1+2][n_1] = p1.z; Wb[nb][kk_1+3][n_1] = p1.w;
                __syncthreads();
            }
        }
        __syncthreads();   // all hT reads of this step complete

        // epilogue: h2h -> out, h = tanh(i2h + h2h) -> hs_out + resident hT
        const size_t base = ((size_t)t * BATCH + bm + tm) * HID;
#pragma unroll
        for (int i = 0; i < 8; i++) {
            const size_t ro = base + (size_t)i * HID;
            float v0,v1,v2,v3,v4,v5,v6,v7;
            unpack2(acc[i][0], v0, v1); unpack2(acc[i][1], v2, v3);
            unpack2(acc[i][2], v4, v5); unpack2(acc[i][3], v6, v7);
            const float4 h0 = make_float4(v0+bb0.x, v1+bb0.y, v2+bb0.z, v3+bb0.w);
            const float4 h1 = make_float4(v4+bb1.x, v5+bb1.y, v6+bb1.z, v7+bb1.w);
            *reinterpret_cast<float4*>(&h2h_seq[ro + tn0]) = h0;
            *reinterpret_cast<float4*>(&h2h_seq[ro + tn1]) = h1;
            const float4 x0 = *reinterpret_cast<const float4*>(&i2h[ro + tn0]);
            const float4 x1 = *reinterpret_cast<const float4*>(&i2h[ro + tn1]);
            const float4 n0v = make_float4(tanhf(x0.x+h0.x), tanhf(x0.y+h0.y),
                                           tanhf(x0.z+h0.z), tanhf(x0.w+h0.w));
            const float4 n1v = make_float4(tanhf(x1.x+h1.x), tanhf(x1.y+h1.y),
                                           tanhf(x1.z+h1.z), tanhf(x1.w+h1.w));
            *reinterpret_cast<float4*>(&hs_out[ro + tn0]) = n0v;
            *reinterpret_cast<float4*>(&hs_out[ro + tn1]) = n1v;
            if (t == T_STEPS - 1) {
                const size_t rh = (size_t)(bm + tm + i) * HID;
                *reinterpret_cast<float4*>(&hc1_out[rh + tn0]) = n0v;
                *reinterpret_cast<float4*>(&hc1_out[rh + tn1]) = n1v;
            }
            const int mi = tm + i;
            hT[(tn0+0)*HP + mi] = n0v.x; hT[(tn0+1)*HP + mi] = n0v.y;
            hT[(tn0+2)*HP + mi] = n0v.z; hT[(tn0+3)*HP + mi] = n0v.w;
            hT[(tn1+0)*HP + mi] = n1v.x; hT[(tn1+1)*HP + mi] = n1v.y;
            hT[(tn1+2)*HP + mi] = n1v.z; hT[(tn1+3)*HP + mi] = n1v.w;
        }
        __syncthreads();   // hT updated before next step reads it
    }
}

// ---------------------------------------------------------------------------
__global__ void __launch_bounds__(256)
fcc_kernel(const float* __restrict__ X, const float* __restrict__ W,
           const float* __restrict__ b, float* __restrict__ out)
{
    __shared__ float Ws[NCLS * OUT_F];
    __shared__ float bs[NCLS];
    const int tid = threadIdx.x;
    for (int i = tid; i < NCLS * OUT_F; i += blockDim.x) Ws[i] = W[i];
    if (tid < NCLS) bs[tid] = b[tid];
    __syncthreads();

    const size_t m = (size_t)blockIdx.x * blockDim.x + tid;
    const float* xr = X + m * OUT_F;

    float acc[NCLS];
#pragma unroll
    for (int c = 0; c < NCLS; c++) acc[c] = bs[c];
#pragma unroll
    for (int k = 0; k < OUT_F; k += 4) {
        const float4 v = *reinterpret_cast<const float4*>(xr + k);
#pragma unroll
        for (int c = 0; c < NCLS; c++) {
            acc[c] += v.x * Ws[c*OUT_F + k+0];
            acc[c] += v.y * Ws[c*OUT_F + k+1];
            acc[c] += v.z * Ws[c*OUT_F + k+2];
            acc[c] += v.w * Ws[c*OUT_F + k+3];
        }
    }
    float4* o = reinterpret_cast<float4*>(out + m * NCLS);
    o[0] = make_float4(acc[0], acc[1], acc[2], acc[3]);
    o[1] = make_float4(acc[4], acc[5], acc[6], acc[7]);
}

__global__ void __launch_bounds__(256)
copy3_kernel(const float4* __restrict__ a, const float4* __restrict__ b,
             const float4* __restrict__ c,
             float4* __restrict__ oa, float4* __restrict__ ob,
             float4* __restrict__ oc)
{
    const size_t i = (size_t)blockIdx.x * blockDim.x + threadIdx.x;
    oa[i] = a[i]; ob[i] = b[i]; oc[i] = c[i];
}

// ---------------------------------------------------------------------------
extern "C" void kernel_launch(void* const* d_in, const int* in_sizes, int n_in,
                              void* d_out, int out_size)
{
    const float* x      = (const float*)d_in[0];
    const float* hc1    = (const float*)d_in[2];
    const float* hc2    = (const float*)d_in[3];
    const float* hc3    = (const float*)d_in[4];
    const float* hc4    = (const float*)d_in[5];
    const float* W_i2h  = (const float*)d_in[6];
    const float* b_i2h  = (const float*)d_in[7];
    const float* W_h2h  = (const float*)d_in[8];
    const float* b_h2h  = (const float*)d_in[9];
    const float* W_h2o  = (const float*)d_in[10];
    const float* b_h2o  = (const float*)d_in[11];
    const float* W_fcc  = (const float*)d_in[12];
    const float* b_fcc  = (const float*)d_in[13];
    float* out = (float*)d_out;

    float *hs, *o64;
    cudaGetSymbolAddress((void**)&hs,  g_hs);
    cudaGetSymbolAddress((void**)&o64, g_out64);

    // pass-throughs
    copy3_kernel<<<(BH/4)/256, 256>>>(
        (const float4*)hc2, (const float4*)hc3, (const float4*)hc4,
        (float4*)(out + OFF_HC2), (float4*)(out + OFF_HC3), (float4*)(out + OFF_HC4));

    // i2h_seq = x @ W_i2h^T + b  [131072 x 256], K=64
    sgemm2<128, 128, 8, 8, 0><<<dim3(MROWS/128, HID/128), 256>>>(
        MROWS, HID, IN_F, x, W_i2h, b_i2h, out + OFF_I2H);

    // persistent fused 16-step recurrence
    const int smem_bytes = (HID*HP + 2*8*HID) * (int)sizeof(float);  // 82,944 B
    cudaFuncSetAttribute(rnn_persist,
                         cudaFuncAttributeMaxDynamicSharedMemorySize, smem_bytes);
    rnn_persist<<<BATCH/64, 256, smem_bytes>>>(
        hc1, W_h2h, b_h2h, out + OFF_I2H,
        out + OFF_H2H, hs, out + OFF_HC1);

    // out64 = tanh(hs @ W_h2o^T + b)  [131072 x 64], K=256
    sgemm2<128, 64, 8, 8, 2><<<dim3(MROWS/128, 1), 128>>>(
        MROWS, OUT_F, HID, hs, W_h2o, b_h2o, o64);

    // output_seq = out64 @ W_fcc^T + b_fcc
    fcc_kernel<<<MROWS/256, 256>>>(o64, W_fcc, b_fcc, out + OFF_OUTSEQ);
}

// round 10
// speedup vs baseline: 2.3902x; 1.3779x over previous
#include <cuda_runtime.h>
#include <cuda_bf16.h>
#include <stdint.h>
#include <math.h>

// ---------------- problem constants ----------------
#define T_STEPS 16
#define BATCH   8192
#define HID     256
#define IN_F    64
#define OUT_F   64
#define NCLS    8
#define MROWS   (T_STEPS*BATCH)
#define BH      (BATCH*HID)

// ---------------- output layout (reference return order, fp32) -------------
#define OFF_OUTSEQ 0
#define LEN_OUTSEQ (T_STEPS*BATCH*NCLS)
#define OFF_HC1    (OFF_OUTSEQ + LEN_OUTSEQ)
#define OFF_HC2    (OFF_HC1 + BH)
#define OFF_HC3    (OFF_HC2 + BH)
#define OFF_HC4    (OFF_HC3 + BH)
#define OFF_I2H    (OFF_HC4 + BH)
#define OFF_H2H    (OFF_I2H + (size_t)T_STEPS*BH)

// ---------------- scratch ----------------
__device__ float g_hs[(size_t)MROWS * HID];
__device__ float g_out64[(size_t)MROWS * OUT_F];
// W_h2h pre-packed B-fragments: [kchunk 16][ntile 32][lane 32] x uint4
// uint4 = {hi(k,k+1), hi(k+8,k+9), lo(k,k+1), lo(k+8,k+9)}
__device__ uint4 g_wfrag[16 * 32 * 32];

// ---------------- f32x2 helpers (for fp32 sgemm path) ----------------------
__device__ __forceinline__ unsigned long long pack2(float lo, float hi) {
    unsigned long long r;
    asm("mov.b64 %0, {%1, %2};" : "=l"(r) : "f"(lo), "f"(hi));
    return r;
}
__device__ __forceinline__ void unpack2(unsigned long long v, float& lo, float& hi) {
    asm("mov.b64 {%0, %1}, %2;" : "=f"(lo), "=f"(hi) : "l"(v));
}
__device__ __forceinline__ void ffma2(unsigned long long& d,
                                      unsigned long long a, unsigned long long b) {
    asm("fma.rn.f32x2 %0, %1, %2, %0;" : "+l"(d) : "l"(a), "l"(b));
}

// ---------------- mma helpers ----------------------------------------------
__device__ __forceinline__ uint32_t smem_u32(const void* p) {
    uint32_t a;
    asm("{ .reg .u64 t; cvta.to.shared.u64 t, %1; cvt.u32.u64 %0, t; }"
        : "=r"(a) : "l"(p));
    return a;
}
__device__ __forceinline__ void ldsm4(uint32_t* r, uint32_t addr) {
    asm volatile("ldmatrix.sync.aligned.m8n8.x4.shared.b16 {%0,%1,%2,%3}, [%4];"
                 : "=r"(r[0]), "=r"(r[1]), "=r"(r[2]), "=r"(r[3]) : "r"(addr));
}
__device__ __forceinline__ void mma16816(float* c, const uint32_t* a,
                                         uint32_t b0, uint32_t b1) {
    asm volatile("mma.sync.aligned.m16n8k16.row.col.f32.bf16.bf16.f32 "
                 "{%0,%1,%2,%3}, {%4,%5,%6,%7}, {%8,%9}, {%0,%1,%2,%3};"
                 : "+f"(c[0]), "+f"(c[1]), "+f"(c[2]), "+f"(c[3])
                 : "r"(a[0]), "r"(a[1]), "r"(a[2]), "r"(a[3]), "r"(b0), "r"(b1));
}
__device__ __forceinline__ uint32_t bfp(float x, float y) {
    __nv_bfloat162 t;
    t.x = __float2bfloat16_rn(x); t.y = __float2bfloat16_rn(y);
    return *reinterpret_cast<uint32_t*>(&t);
}

// ---------------------------------------------------------------------------
// Prep: pack W_h2h [256n][256k] fp32 into bf16 hi/lo B-fragments.
// lane l of (c,j): n = j*8 + l/4, k0 = c*16 + (l%4)*2, k8 = k0+8.
// ---------------------------------------------------------------------------
__global__ void __launch_bounds__(256)
prep_wfrag(const float* __restrict__ W)
{
    const int idx = blockIdx.x * 256 + threadIdx.x;   // 0..16383
    const int l = idx & 31, j = (idx >> 5) & 31, c = idx >> 10;
    const int n  = j * 8 + (l >> 2);
    const int k0 = c * 16 + (l & 3) * 2;
    const float w00 = W[n*HID + k0],     w01 = W[n*HID + k0 + 1];
    const float w10 = W[n*HID + k0 + 8], w11 = W[n*HID + k0 + 9];
    const float h00 = __bfloat162float(__float2bfloat16_rn(w00));
    const float h01 = __bfloat162float(__float2bfloat16_rn(w01));
    const float h10 = __bfloat162float(__float2bfloat16_rn(w10));
    const float h11 = __bfloat162float(__float2bfloat16_rn(w11));
    uint4 v;
    v.x = bfp(w00, w01);
    v.y = bfp(w10, w11);
    v.z = bfp(w00 - h00, w01 - h01);
    v.w = bfp(w10 - h10, w11 - h11);
    g_wfrag[idx] = v;
}

// ---------------------------------------------------------------------------
// Persistent tensor-core Elman recurrence. 128 CTAs x 256 thr, M=64 rows/CTA.
// A = h as bf16 hi/lo SMEM images. Row stride APAD=264 bf16 ELEMENTS (528 B;
// 528 mod 128 = 16 -> the 8 ldmatrix row addresses hit distinct 16B phases:
// conflict-free). B = prepacked W fragments, double-buffered SMEM.
// ---------------------------------------------------------------------------
#define APAD 264                      // bf16 elements per A row (>= HID=256)
#define SM_ALO (64*APAD)              // element offset of Alo
#define SM_BST (2*64*APAD*2)          // byte offset of Bst (= 67584)
#define RNN_SMEM (SM_BST + 2*1024*16) // + 32 KB B double-buffer = 100352

__global__ void __launch_bounds__(256)
rnn_mma(const float* __restrict__ hc1, const uint4* __restrict__ Wfrag,
        const float* __restrict__ bias, const float* __restrict__ i2h,
        float* __restrict__ h2h_seq, float* __restrict__ hs_out,
        float* __restrict__ hc1_out)
{
    extern __shared__ char sm8[];
    __nv_bfloat16* Ahi = (__nv_bfloat16*)sm8;
    __nv_bfloat16* Alo = Ahi + SM_ALO;
    uint4* Bst = (uint4*)(sm8 + SM_BST);          // [2][32j*32l]

    const int tid = threadIdx.x;
    const int l   = tid & 31;
    const int wid = tid >> 5;
    const int wm  = wid & 1;        // m-half: rows wm*32..+31
    const int wn  = wid >> 1;       // n-quarter: cols wn*64..+63
    const int bm  = blockIdx.x * 64;

    // prologue: split hc1 rows into Ahi/Alo
    for (int i = tid; i < 64 * 128; i += 256) {
        const int m = i >> 7, kp = (i & 127) * 2;
        const float2 v = *reinterpret_cast<const float2*>(&hc1[(size_t)(bm+m)*HID + kp]);
        const float hx = __bfloat162float(__float2bfloat16_rn(v.x));
        const float hy = __bfloat162float(__float2bfloat16_rn(v.y));
        *reinterpret_cast<uint32_t*>(&Ahi[m*APAD + kp]) = bfp(v.x, v.y);
        *reinterpret_cast<uint32_t*>(&Alo[m*APAD + kp]) = bfp(v.x - hx, v.y - hy);
    }

    // per-thread bias pairs for its 8 n-tiles
    float2 bias2[8];
#pragma unroll
    for (int nt = 0; nt < 8; nt++)
        bias2[nt] = *reinterpret_cast<const float2*>(&bias[wn*64 + nt*8 + (l&3)*2]);

    const uint32_t aHiBase = smem_u32(Ahi);
    const uint32_t aLoBase = smem_u32(Alo);
    const int mi = l >> 3, rr8 = l & 7;
    // ldmatrix byte offset within a (mt, kchunk) tile:
    // matrix 0: rows 0-7,col 0 | 1: rows 8-15,col 0 | 2: rows 0-7,col 8 | 3: rows 8-15,col 8
    const uint32_t ldsmOff = (uint32_t)((((mi & 1) * 8 + rr8) * APAD + (mi >> 1) * 8) * 2);

    __syncthreads();

#pragma unroll 1
    for (int t = 0; t < T_STEPS; t++) {
        // stage k-chunk 0 into buffer 0
#pragma unroll
        for (int r = 0; r < 4; r++) Bst[tid + r*256] = Wfrag[tid + r*256];
        __syncthreads();

        float acc[2][8][4];
#pragma unroll
        for (int a = 0; a < 2; a++)
#pragma unroll
            for (int b = 0; b < 8; b++)
#pragma unroll
                for (int d = 0; d < 4; d++) acc[a][b][d] = 0.0f;

#pragma unroll 1
        for (int c = 0; c < 16; c++) {
            uint4 pre[4];
            if (c < 15) {
#pragma unroll
                for (int r = 0; r < 4; r++)
                    pre[r] = Wfrag[(c+1)*1024 + tid + r*256];
            }
            // A fragments for this k-chunk (2 m-tiles x hi/lo)
            uint32_t ah[2][4], al[2][4];
#pragma unroll
            for (int mt = 0; mt < 2; mt++) {
                const uint32_t rowByte = (uint32_t)(((wm*32 + mt*16) * APAD + c*16) * 2);
                ldsm4(ah[mt], aHiBase + rowByte + ldsmOff);
                ldsm4(al[mt], aLoBase + rowByte + ldsmOff);
            }
            const uint4* bbuf = Bst + (c & 1) * 1024;
#pragma unroll
            for (int nt = 0; nt < 8; nt++) {
                const uint4 b = bbuf[(wn*8 + nt)*32 + l];
#pragma unroll
                for (int mt = 0; mt < 2; mt++) {
                    mma16816(acc[mt][nt], ah[mt], b.x, b.y);   // Ah*Bh
                    mma16816(acc[mt][nt], ah[mt], b.z, b.w);   // Ah*Bl
                    mma16816(acc[mt][nt], al[mt], b.x, b.y);   // Al*Bh
                }
            }
            if (c < 15) {
                uint4* nb = Bst + ((c+1) & 1) * 1024;
#pragma unroll
                for (int r = 0; r < 4; r++) nb[tid + r*256] = pre[r];
                __syncthreads();
            }
        }
        __syncthreads();   // all A reads done before epilogue rewrites A

        // epilogue
#pragma unroll
        for (int mt = 0; mt < 2; mt++) {
            const int m0 = wm*32 + mt*16 + (l >> 2);
#pragma unroll
            for (int nt = 0; nt < 8; nt++) {
                const int n = wn*64 + nt*8 + (l & 3)*2;
                const float2 bv = bias2[nt];
#pragma unroll
                for (int rr = 0; rr < 2; rr++) {
                    const int mrel = m0 + rr*8;
                    const float vx = acc[mt][nt][rr*2+0] + bv.x;
                    const float vy = acc[mt][nt][rr*2+1] + bv.y;
                    const size_t gi = ((size_t)t*BATCH + bm + mrel)*HID + n;
                    *reinterpret_cast<float2*>(&h2h_seq[gi]) = make_float2(vx, vy);
                    const float2 xi = *reinterpret_cast<const float2*>(&i2h[gi]);
                    const float h0 = tanhf(xi.x + vx);
                    const float h1 = tanhf(xi.y + vy);
                    *reinterpret_cast<float2*>(&hs_out[gi]) = make_float2(h0, h1);
                    if (t == T_STEPS - 1)
                        *reinterpret_cast<float2*>(&hc1_out[(size_t)(bm+mrel)*HID + n])
                            = make_float2(h0, h1);
                    const float e0 = __bfloat162float(__float2bfloat16_rn(h0));
                    const float e1 = __bfloat162float(__float2bfloat16_rn(h1));
                    *reinterpret_cast<uint32_t*>(&Ahi[mrel*APAD + n]) = bfp(h0, h1);
                    *reinterpret_cast<uint32_t*>(&Alo[mrel*APAD + n]) = bfp(h0-e0, h1-e1);
                }
            }
        }
        __syncthreads();   // A updated before next step's ldmatrix
    }
}

// ---------------------------------------------------------------------------
// f32x2 register-blocked SGEMM: C = A @ Bm^T + bias (+tanh)
// ---------------------------------------------------------------------------
template<int BM, int BN, int BK, int TM, int MODE>
__global__ void __launch_bounds__((BM/TM)*(BN/8))
sgemm2(int M, int N, int K,
       const float* __restrict__ A,
       const float* __restrict__ Bm,
       const float* __restrict__ bias,
       float* __restrict__ C)
{
    constexpr int THREADS = (BM/TM)*(BN/8);
    constexpr int NG = BN/8;
    __shared__ float As[BK][BM];
    __shared__ float Bs[BK][BN];

    const int tid = threadIdx.x;
    const int bm  = blockIdx.x * BM;
    const int bn  = blockIdx.y * BN;
    const int tn0 = (tid % NG) * 4;
    const int tn1 = tn0 + BN/2;
    const int tm  = (tid / NG) * TM;

    unsigned long long acc[TM][4];
#pragma unroll
    for (int i = 0; i < TM; i++)
#pragma unroll
        for (int j = 0; j < 4; j++) acc[i][j] = 0ull;

    for (int k0 = 0; k0 < K; k0 += BK) {
        for (int i = tid * 4; i < BM * BK; i += THREADS * 4) {
            int row = i / BK, kk = i % BK;
            const float4 v = *reinterpret_cast<const float4*>(
                &A[(size_t)(bm + row) * K + k0 + kk]);
            As[kk+0][row] = v.x; As[kk+1][row] = v.y;
            As[kk+2][row] = v.z; As[kk+3][row] = v.w;
        }
        for (int i = tid * 4; i < BN * BK; i += THREADS * 4) {
            int row = i / BK, kk = i % BK;
            const float4 v = *reinterpret_cast<const float4*>(
                &Bm[(size_t)(bn + row) * K + k0 + kk]);
            Bs[kk+0][row] = v.x; Bs[kk+1][row] = v.y;
            Bs[kk+2][row] = v.z; Bs[kk+3][row] = v.w;
        }
        __syncthreads();
#pragma unroll
        for (int kk = 0; kk < BK; kk++) {
            const ulonglong2 b0 = *reinterpret_cast<const ulonglong2*>(&Bs[kk][tn0]);
            const ulonglong2 b1 = *reinterpret_cast<const ulonglong2*>(&Bs[kk][tn1]);
#pragma unroll
            for (int i = 0; i < TM; i++) {
                const float a = As[kk][tm + i];
                const unsigned long long a2 = pack2(a, a);
                ffma2(acc[i][0], a2, b0.x);
                ffma2(acc[i][1], a2, b0.y);
                ffma2(acc[i][2], a2, b1.x);
                ffma2(acc[i][3], a2, b1.y);
            }
        }
        __syncthreads();
    }

    const float4 bb0 = *reinterpret_cast<const float4*>(&bias[bn + tn0]);
    const float4 bb1 = *reinterpret_cast<const float4*>(&bias[bn + tn1]);
#pragma unroll
    for (int i = 0; i < TM; i++) {
        const size_t ro = (size_t)(bm + tm + i) * N + bn;
        float v0,v1,v2,v3,v4,v5,v6,v7;
        unpack2(acc[i][0], v0, v1); unpack2(acc[i][1], v2, v3);
        unpack2(acc[i][2], v4, v5); unpack2(acc[i][3], v6, v7);
        float4 r0 = make_float4(v0+bb0.x, v1+bb0.y, v2+bb0.z, v3+bb0.w);
        float4 r1 = make_float4(v4+bb1.x, v5+bb1.y, v6+bb1.z, v7+bb1.w);
        if (MODE == 2) {
            r0.x = tanhf(r0.x); r0.y = tanhf(r0.y); r0.z = tanhf(r0.z); r0.w = tanhf(r0.w);
            r1.x = tanhf(r1.x); r1.y = tanhf(r1.y); r1.z = tanhf(r1.z); r1.w = tanhf(r1.w);
        }
        *reinterpret_cast<float4*>(&C[ro + tn0]) = r0;
        *reinterpret_cast<float4*>(&C[ro + tn1]) = r1;
    }
}

// ---------------------------------------------------------------------------
__global__ void __launch_bounds__(256)
fcc_kernel(const float* __restrict__ X, const float* __restrict__ W,
           const float* __restrict__ b, float* __restrict__ out)
{
    __shared__ float Ws[NCLS * OUT_F];
    __shared__ float bs[NCLS];
    const int tid = threadIdx.x;
    for (int i = tid; i < NCLS * OUT_F; i += blockDim.x) Ws[i] = W[i];
    if (tid < NCLS) bs[tid] = b[tid];
    __syncthreads();

    const size_t m = (size_t)blockIdx.x * blockDim.x + tid;
    const float* xr = X + m * OUT_F;
    float acc[NCLS];
#pragma unroll
    for (int c = 0; c < NCLS; c++) acc[c] = bs[c];
#pragma unroll
    for (int k = 0; k < OUT_F; k += 4) {
        const float4 v = *reinterpret_cast<const float4*>(xr + k);
#pragma unroll
        for (int c = 0; c < NCLS; c++) {
            acc[c] += v.x * Ws[c*OUT_F + k+0];
            acc[c] += v.y * Ws[c*OUT_F + k+1];
            acc[c] += v.z * Ws[c*OUT_F + k+2];
            acc[c] += v.w * Ws[c*OUT_F + k+3];
        }
    }
    float4* o = reinterpret_cast<float4*>(out + m * NCLS);
    o[0] = make_float4(acc[0], acc[1], acc[2], acc[3]);
    o[1] = make_float4(acc[4], acc[5], acc[6], acc[7]);
}

__global__ void __launch_bounds__(256)
copy3_kernel(const float4* __restrict__ a, const float4* __restrict__ b,
             const float4* __restrict__ c,
             float4* __restrict__ oa, float4* __restrict__ ob,
             float4* __restrict__ oc)
{
    const size_t i = (size_t)blockIdx.x * blockDim.x + threadIdx.x;
    oa[i] = a[i]; ob[i] = b[i]; oc[i] = c[i];
}

// ---------------------------------------------------------------------------
extern "C" void kernel_launch(void* const* d_in, const int* in_sizes, int n_in,
                              void* d_out, int out_size)
{
    const float* x      = (const float*)d_in[0];
    const float* hc1    = (const float*)d_in[2];
    const float* hc2    = (const float*)d_in[3];
    const float* hc3    = (const float*)d_in[4];
    const float* hc4    = (const float*)d_in[5];
    const float* W_i2h  = (const float*)d_in[6];
    const float* b_i2h  = (const float*)d_in[7];
    const float* W_h2h  = (const float*)d_in[8];
    const float* b_h2h  = (const float*)d_in[9];
    const float* W_h2o  = (const float*)d_in[10];
    const float* b_h2o  = (const float*)d_in[11];
    const float* W_fcc  = (const float*)d_in[12];
    const float* b_fcc  = (const float*)d_in[13];
    float* out = (float*)d_out;

    float *hs, *o64; uint4* wfrag;
    cudaGetSymbolAddress((void**)&hs,    g_hs);
    cudaGetSymbolAddress((void**)&o64,   g_out64);
    cudaGetSymbolAddress((void**)&wfrag, g_wfrag);

    // pass-throughs + W fragment prep
    copy3_kernel<<<(BH/4)/256, 256>>>(
        (const float4*)hc2, (const float4*)hc3, (const float4*)hc4,
        (float4*)(out + OFF_HC2), (float4*)(out + OFF_HC3), (float4*)(out + OFF_HC4));
    prep_wfrag<<<64, 256>>>(W_h2h);

    // i2h_seq = x @ W_i2h^T + b  [131072 x 256], K=64
    sgemm2<128, 128, 8, 8, 0><<<dim3(MROWS/128, HID/128), 256>>>(
        MROWS, HID, IN_F, x, W_i2h, b_i2h, out + OFF_I2H);

    // persistent tensor-core 16-step recurrence
    cudaFuncSetAttribute(rnn_mma,
                         cudaFuncAttributeMaxDynamicSharedMemorySize, RNN_SMEM);
    rnn_mma<<<BATCH/64, 256, RNN_SMEM>>>(
        hc1, wfrag, b_h2h, out + OFF_I2H,
        out + OFF_H2H, hs, out + OFF_HC1);

    // out64 = tanh(hs @ W_h2o^T + b)  [131072 x 64], K=256
    sgemm2<128, 64, 8, 8, 2><<<dim3(MROWS/128, 1), 128>>>(
        MROWS, OUT_F, HID, hs, W_h2o, b_h2o, o64);

    // output_seq = out64 @ W_fcc^T + b_fcc
    fcc_kernel<<<MROWS/256, 256>>>(o64, W_fcc, b_fcc, out + OFF_OUTSEQ);
}

// round 13
// speedup vs baseline: 3.0088x; 1.2588x over previous
#include <cuda_runtime.h>
#include <cuda_bf16.h>
#include <stdint.h>
#include <math.h>

// ---------------- problem constants ----------------
#define T_STEPS 16
#define BATCH   8192
#define HID     256
#define IN_F    64
#define OUT_F   64
#define NCLS    8
#define MROWS   (T_STEPS*BATCH)
#define BH      (BATCH*HID)

// ---------------- output layout (reference return order, fp32) -------------
#define OFF_OUTSEQ 0
#define LEN_OUTSEQ (T_STEPS*BATCH*NCLS)
#define OFF_HC1    (OFF_OUTSEQ + LEN_OUTSEQ)
#define OFF_HC2    (OFF_HC1 + BH)
#define OFF_HC3    (OFF_HC2 + BH)
#define OFF_HC4    (OFF_HC3 + BH)
#define OFF_I2H    (OFF_HC4 + BH)
#define OFF_H2H    (OFF_I2H + (size_t)T_STEPS*BH)

// ---------------- scratch ----------------
// hidden states as packed bf16 pairs (hi/lo split), [MROWS][128] uint32 each
__device__ uint32_t g_hsHi[(size_t)MROWS * (HID/2)];
__device__ uint32_t g_hsLo[(size_t)MROWS * (HID/2)];
__device__ float    g_out64[(size_t)MROWS * OUT_F];
// W_h2h B-fragments: [kchunk 16][ntile 32][lane 32] uint4
__device__ uint4 g_wfrag [16 * 32 * 32];
// W_h2o B-fragments: [kchunk 16][ntile 8][lane 32] uint4
__device__ uint4 g_wfragO[16 * 8 * 32];

// ---------------- f32x2 helpers (fp32 sgemm path) ---------------------------
__device__ __forceinline__ unsigned long long pack2(float lo, float hi) {
    unsigned long long r;
    asm("mov.b64 %0, {%1, %2};" : "=l"(r) : "f"(lo), "f"(hi));
    return r;
}
__device__ __forceinline__ void unpack2(unsigned long long v, float& lo, float& hi) {
    asm("mov.b64 {%0, %1}, %2;" : "=f"(lo), "=f"(hi) : "l"(v));
}
__device__ __forceinline__ void ffma2(unsigned long long& d,
                                      unsigned long long a, unsigned long long b) {
    asm("fma.rn.f32x2 %0, %1, %2, %0;" : "+l"(d) : "l"(a), "l"(b));
}

// ---------------- mma helpers ----------------------------------------------
__device__ __forceinline__ uint32_t smem_u32(const void* p) {
    uint32_t a;
    asm("{ .reg .u64 t; cvta.to.shared.u64 t, %1; cvt.u32.u64 %0, t; }"
        : "=r"(a) : "l"(p));
    return a;
}
__device__ __forceinline__ void ldsm4(uint32_t* r, uint32_t addr) {
    asm volatile("ldmatrix.sync.aligned.m8n8.x4.shared.b16 {%0,%1,%2,%3}, [%4];"
                 : "=r"(r[0]), "=r"(r[1]), "=r"(r[2]), "=r"(r[3]) : "r"(addr));
}
__device__ __forceinline__ void mma16816(float* c, const uint32_t* a,
                                         uint32_t b0, uint32_t b1) {
    asm volatile("mma.sync.aligned.m16n8k16.row.col.f32.bf16.bf16.f32 "
                 "{%0,%1,%2,%3}, {%4,%5,%6,%7}, {%8,%9}, {%0,%1,%2,%3};"
                 : "+f"(c[0]), "+f"(c[1]), "+f"(c[2]), "+f"(c[3])
                 : "r"(a[0]), "r"(a[1]), "r"(a[2]), "r"(a[3]), "r"(b0), "r"(b1));
}
__device__ __forceinline__ uint32_t bfp(float x, float y) {
    __nv_bfloat162 t;
    t.x = __float2bfloat16_rn(x); t.y = __float2bfloat16_rn(y);
    return *reinterpret_cast<uint32_t*>(&t);
}

// ---------------------------------------------------------------------------
// Prep: pack W [N x 256] fp32 into bf16 hi/lo B-fragments.
// njt = N/8 tiles. Frag layout: [c][j][l], lane l of (c,j):
//   n = j*8 + l/4, k0 = c*16 + (l%4)*2; uint4 = {hi(k0),hi(k0+8),lo(k0),lo(k0+8)}
// ---------------------------------------------------------------------------
__global__ void __launch_bounds__(256)
prep_frag(const float* __restrict__ W, uint4* __restrict__ outF, int njt)
{
    const int idx = blockIdx.x * 256 + threadIdx.x;
    const int l = idx & 31, g = idx >> 5;
    const int j = g % njt, c = g / njt;
    const int n  = j * 8 + (l >> 2);
    const int k0 = c * 16 + (l & 3) * 2;
    const float w00 = W[n*HID + k0],     w01 = W[n*HID + k0 + 1];
    const float w10 = W[n*HID + k0 + 8], w11 = W[n*HID + k0 + 9];
    const float h00 = __bfloat162float(__float2bfloat16_rn(w00));
    const float h01 = __bfloat162float(__float2bfloat16_rn(w01));
    const float h10 = __bfloat162float(__float2bfloat16_rn(w10));
    const float h11 = __bfloat162float(__float2bfloat16_rn(w11));
    uint4 v;
    v.x = bfp(w00, w01);
    v.y = bfp(w10, w11);
    v.z = bfp(w00 - h00, w01 - h01);
    v.w = bfp(w10 - h10, w11 - h11);
    outF[(c * njt + j) * 32 + l] = v;
}

// ---------------------------------------------------------------------------
// Persistent tensor-core Elman recurrence. 128 CTAs x 512 thr (16 warps),
// M=64 rows/CTA. A = h in SMEM bf16 hi/lo images (APAD=264 elem stride ->
// conflict-free ldmatrix). B loaded per-warp directly from g_wfrag (no SMEM
// staging, no per-chunk barriers). Warp tile 32m x 32n.
// ---------------------------------------------------------------------------
#define APAD 264
#define SM_ALO (64*APAD)
#define RNN_SMEM (2*64*APAD*2)        // 67,584 B

__global__ void __launch_bounds__(512)
rnn_mma(const float* __restrict__ hc1, const uint4* __restrict__ Wfrag,
        const float* __restrict__ bias, const float* __restrict__ i2h,
        float* __restrict__ h2h_seq,
        uint32_t* __restrict__ hsHi, uint32_t* __restrict__ hsLo,
        float* __restrict__ hc1_out)
{
    extern __shared__ char sm8[];
    __nv_bfloat16* Ahi = (__nv_bfloat16*)sm8;
    __nv_bfloat16* Alo = Ahi + SM_ALO;

    const int tid = threadIdx.x;
    const int l   = tid & 31;
    const int wid = tid >> 5;
    const int wm  = wid & 1;        // m-half: rows wm*32..+31
    const int wn  = wid >> 1;       // n-slice: cols wn*32..+31 (4 ntiles)
    const int bm  = blockIdx.x * 64;

    // prologue: split hc1 rows into Ahi/Alo
    for (int i = tid; i < 64 * 128; i += 512) {
        const int m = i >> 7, kp = (i & 127) * 2;
        const float2 v = *reinterpret_cast<const float2*>(&hc1[(size_t)(bm+m)*HID + kp]);
        const float hx = __bfloat162float(__float2bfloat16_rn(v.x));
        const float hy = __bfloat162float(__float2bfloat16_rn(v.y));
        *reinterpret_cast<uint32_t*>(&Ahi[m*APAD + kp]) = bfp(v.x, v.y);
        *reinterpret_cast<uint32_t*>(&Alo[m*APAD + kp]) = bfp(v.x - hx, v.y - hy);
    }

    float2 bias2[4];
#pragma unroll
    for (int nt = 0; nt < 4; nt++)
        bias2[nt] = *reinterpret_cast<const float2*>(&bias[wn*32 + nt*8 + (l&3)*2]);

    const uint32_t aHiBase = smem_u32(Ahi);
    const uint32_t aLoBase = smem_u32(Alo);
    const int mi = l >> 3, rr8 = l & 7;
    const uint32_t ldsmOff = (uint32_t)((((mi & 1) * 8 + rr8) * APAD + (mi >> 1) * 8) * 2);
    const uint4* wbase = Wfrag + (wn * 4) * 32 + l;   // + c*1024 + nt*32

    __syncthreads();

#pragma unroll 1
    for (int t = 0; t < T_STEPS; t++) {
        float acc[2][4][4];
#pragma unroll
        for (int a = 0; a < 2; a++)
#pragma unroll
            for (int b = 0; b < 4; b++)
#pragma unroll
                for (int d = 0; d < 4; d++) acc[a][b][d] = 0.0f;

        uint4 bcur[4];
#pragma unroll
        for (int nt = 0; nt < 4; nt++) bcur[nt] = wbase[nt*32];

#pragma unroll 1
        for (int c = 0; c < 16; c++) {
            uint4 bnext[4];
            if (c < 15) {
#pragma unroll
                for (int nt = 0; nt < 4; nt++)
                    bnext[nt] = wbase[(c+1)*1024 + nt*32];
            }
            uint32_t ah[2][4], al[2][4];
#pragma unroll
            for (int mt = 0; mt < 2; mt++) {
                const uint32_t rowByte = (uint32_t)(((wm*32 + mt*16) * APAD + c*16) * 2);
                ldsm4(ah[mt], aHiBase + rowByte + ldsmOff);
                ldsm4(al[mt], aLoBase + rowByte + ldsmOff);
            }
#pragma unroll
            for (int nt = 0; nt < 4; nt++) {
#pragma unroll
                for (int mt = 0; mt < 2; mt++) {
                    mma16816(acc[mt][nt], ah[mt], bcur[nt].x, bcur[nt].y);  // Ah*Bh
                    mma16816(acc[mt][nt], ah[mt], bcur[nt].z, bcur[nt].w);  // Ah*Bl
                    mma16816(acc[mt][nt], al[mt], bcur[nt].x, bcur[nt].y);  // Al*Bh
                }
            }
#pragma unroll
            for (int nt = 0; nt < 4; nt++) bcur[nt] = bnext[nt];
        }
        __syncthreads();   // all A reads of this step done

        // epilogue
#pragma unroll
        for (int mt = 0; mt < 2; mt++) {
            const int m0 = wm*32 + mt*16 + (l >> 2);
#pragma unroll
            for (int nt = 0; nt < 4; nt++) {
                const int n = wn*32 + nt*8 + (l & 3)*2;
                const float2 bv = bias2[nt];
#pragma unroll
                for (int rr = 0; rr < 2; rr++) {
                    const int mrel = m0 + rr*8;
                    const float vx = acc[mt][nt][rr*2+0] + bv.x;
                    const float vy = acc[mt][nt][rr*2+1] + bv.y;
                    const size_t gi = ((size_t)t*BATCH + bm + mrel)*HID + n;
                    *reinterpret_cast<float2*>(&h2h_seq[gi]) = make_float2(vx, vy);
                    const float2 xi = *reinterpret_cast<const float2*>(&i2h[gi]);
                    const float h0 = tanhf(xi.x + vx);
                    const float h1 = tanhf(xi.y + vy);
                    const float e0 = __bfloat162float(__float2bfloat16_rn(h0));
                    const float e1 = __bfloat162float(__float2bfloat16_rn(h1));
                    const uint32_t phi = bfp(h0, h1);
                    const uint32_t plo = bfp(h0-e0, h1-e1);
                    hsHi[gi >> 1] = phi;
                    hsLo[gi >> 1] = plo;
                    if (t == T_STEPS - 1)
                        *reinterpret_cast<float2*>(&hc1_out[(size_t)(bm+mrel)*HID + n])
                            = make_float2(h0, h1);
                    *reinterpret_cast<uint32_t*>(&Ahi[mrel*APAD + n]) = phi;
                    *reinterpret_cast<uint32_t*>(&Alo[mrel*APAD + n]) = plo;
                }
            }
        }
        __syncthreads();   // A updated before next step's ldmatrix
    }
}

// ---------------------------------------------------------------------------
// h2o HMMA kernel: o64 = tanh(hs @ W_h2o^T + b). 1024 CTAs x 256 thr.
// A fragments loaded directly from packed bf16 hi/lo global arrays.
// Warp tile: 16 rows x 64 cols.
// ---------------------------------------------------------------------------
__global__ void __launch_bounds__(256)
h2o_mma(const uint32_t* __restrict__ Hhi, const uint32_t* __restrict__ Hlo,
        const uint4* __restrict__ WfragO, const float* __restrict__ bias,
        float* __restrict__ o64)
{
    const int tid = threadIdx.x;
    const int l   = tid & 31;
    const int wid = tid >> 5;
    const int bm  = blockIdx.x * 128;

    float acc[8][4];
#pragma unroll
    for (int b = 0; b < 8; b++)
#pragma unroll
        for (int d = 0; d < 4; d++) acc[b][d] = 0.0f;

    const int row0 = bm + wid*16 + (l >> 2);
    const size_t r0b = (size_t)row0 * (HID/2);
    const size_t r1b = r0b + 8 * (HID/2);
    const int kb = (l & 3);
    const uint4* wb = WfragO + l;

#pragma unroll 1
    for (int c = 0; c < 16; c++) {
        uint32_t ah[4], al[4];
        const int base = c*8 + kb;
        ah[0] = Hhi[r0b + base];   ah[1] = Hhi[r1b + base];
        ah[2] = Hhi[r0b + base+4]; ah[3] = Hhi[r1b + base+4];
        al[0] = Hlo[r0b + base];   al[1] = Hlo[r1b + base];
        al[2] = Hlo[r0b + base+4]; al[3] = Hlo[r1b + base+4];
#pragma unroll
        for (int nt = 0; nt < 8; nt++) {
            const uint4 b = wb[(c*8 + nt)*32];
            mma16816(acc[nt], ah, b.x, b.y);
            mma16816(acc[nt], ah, b.z, b.w);
            mma16816(acc[nt], al, b.x, b.y);
        }
    }

    // epilogue: tanh + store
#pragma unroll
    for (int nt = 0; nt < 8; nt++) {
        const int n = nt*8 + (l & 3)*2;
        const float2 bv = *reinterpret_cast<const float2*>(&bias[n]);
#pragma unroll
        for (int rr = 0; rr < 2; rr++) {
            const int row = bm + wid*16 + (l >> 2) + rr*8;
            const float v0 = tanhf(acc[nt][rr*2+0] + bv.x);
            const float v1 = tanhf(acc[nt][rr*2+1] + bv.y);
            *reinterpret_cast<float2*>(&o64[(size_t)row*OUT_F + n]) = make_float2(v0, v1);
        }
    }
}

// ---------------------------------------------------------------------------
// f32x2 register-blocked SGEMM (i2h path): C = A @ Bm^T + bias
// ---------------------------------------------------------------------------
template<int BM, int BN, int BK, int TM, int MODE>
__global__ void __launch_bounds__((BM/TM)*(BN/8))
sgemm2(int M, int N, int K,
       const float* __restrict__ A,
       const float* __restrict__ Bm,
       const float* __restrict__ bias,
       float* __restrict__ C)
{
    constexpr int THREADS = (BM/TM)*(BN/8);
    constexpr int NG = BN/8;
    __shared__ float As[BK][BM];
    __shared__ float Bs[BK][BN];

    const int tid = threadIdx.x;
    const int bm  = blockIdx.x * BM;
    const int bn  = blockIdx.y * BN;
    const int tn0 = (tid % NG) * 4;
    const int tn1 = tn0 + BN/2;
    const int tm  = (tid / NG) * TM;

    unsigned long long acc[TM][4];
#pragma unroll
    for (int i = 0; i < TM; i++)
#pragma unroll
        for (int j = 0; j < 4; j++) acc[i][j] = 0ull;

    for (int k0 = 0; k0 < K; k0 += BK) {
        for (int i = tid * 4; i < BM * BK; i += THREADS * 4) {
            int row = i / BK, kk = i % BK;
            const float4 v = *reinterpret_cast<const float4*>(
                &A[(size_t)(bm + row) * K + k0 + kk]);
            As[kk+0][row] = v.x; As[kk+1][row] = v.y;
            As[kk+2][row] = v.z; As[kk+3][row] = v.w;
        }
        for (int i = tid * 4; i < BN * BK; i += THREADS * 4) {
            int row = i / BK, kk = i % BK;
            const float4 v = *reinterpret_cast<const float4*>(
                &Bm[(size_t)(bn + row) * K + k0 + kk]);
            Bs[kk+0][row] = v.x; Bs[kk+1][row] = v.y;
            Bs[kk+2][row] = v.z; Bs[kk+3][row] = v.w;
        }
        __syncthreads();
#pragma unroll
        for (int kk = 0; kk < BK; kk++) {
            const ulonglong2 b0 = *reinterpret_cast<const ulonglong2*>(&Bs[kk][tn0]);
            const ulonglong2 b1 = *reinterpret_cast<const ulonglong2*>(&Bs[kk][tn1]);
#pragma unroll
            for (int i = 0; i < TM; i++) {
                const float a = As[kk][tm + i];
                const unsigned long long a2 = pack2(a, a);
                ffma2(acc[i][0], a2, b0.x);
                ffma2(acc[i][1], a2, b0.y);
                ffma2(acc[i][2], a2, b1.x);
                ffma2(acc[i][3], a2, b1.y);
            }
        }
        __syncthreads();
    }

    const float4 bb0 = *reinterpret_cast<const float4*>(&bias[bn + tn0]);
    const float4 bb1 = *reinterpret_cast<const float4*>(&bias[bn + tn1]);
#pragma unroll
    for (int i = 0; i < TM; i++) {
        const size_t ro = (size_t)(bm + tm + i) * N + bn;
        float v0,v1,v2,v3,v4,v5,v6,v7;
        unpack2(acc[i][0], v0, v1); unpack2(acc[i][1], v2, v3);
        unpack2(acc[i][2], v4, v5); unpack2(acc[i][3], v6, v7);
        float4 r0 = make_float4(v0+bb0.x, v1+bb0.y, v2+bb0.z, v3+bb0.w);
        float4 r1 = make_float4(v4+bb1.x, v5+bb1.y, v6+bb1.z, v7+bb1.w);
        if (MODE == 2) {
            r0.x = tanhf(r0.x); r0.y = tanhf(r0.y); r0.z = tanhf(r0.z); r0.w = tanhf(r0.w);
            r1.x = tanhf(r1.x); r1.y = tanhf(r1.y); r1.z = tanhf(r1.z); r1.w = tanhf(r1.w);
        }
        *reinterpret_cast<float4*>(&C[ro + tn0]) = r0;
        *reinterpret_cast<float4*>(&C[ro + tn1]) = r1;
    }
}

// ---------------------------------------------------------------------------
__global__ void __launch_bounds__(256)
fcc_kernel(const float* __restrict__ X, const float* __restrict__ W,
           const float* __restrict__ b, float* __restrict__ out)
{
    __shared__ float Ws[NCLS * OUT_F];
    __shared__ float bs[NCLS];
    const int tid = threadIdx.x;
    for (int i = tid; i < NCLS * OUT_F; i += blockDim.x) Ws[i] = W[i];
    if (tid < NCLS) bs[tid] = b[tid];
    __syncthreads();

    const size_t m = (size_t)blockIdx.x * blockDim.x + tid;
    const float* xr = X + m * OUT_F;
    float acc[NCLS];
#pragma unroll
    for (int c = 0; c < NCLS; c++) acc[c] = bs[c];
#pragma unroll
    for (int k = 0; k < OUT_F; k += 4) {
        const float4 v = *reinterpret_cast<const float4*>(xr + k);
#pragma unroll
        for (int c = 0; c < NCLS; c++) {
            acc[c] += v.x * Ws[c*OUT_F + k+0];
            acc[c] += v.y * Ws[c*OUT_F + k+1];
            acc[c] += v.z * Ws[c*OUT_F + k+2];
            acc[c] += v.w * Ws[c*OUT_F + k+3];
        }
    }
    float4* o = reinterpret_cast<float4*>(out + m * NCLS);
    o[0] = make_float4(acc[0], acc[1], acc[2], acc[3]);
    o[1] = make_float4(acc[4], acc[5], acc[6], acc[7]);
}

__global__ void __launch_bounds__(256)
copy3_kernel(const float4* __restrict__ a, const float4* __restrict__ b,
             const float4* __restrict__ c,
             float4* __restrict__ oa, float4* __restrict__ ob,
             float4* __restrict__ oc)
{
    const size_t i = (size_t)blockIdx.x * blockDim.x + threadIdx.x;
    oa[i] = a[i]; ob[i] = b[i]; oc[i] = c[i];
}

// ---------------------------------------------------------------------------
extern "C" void kernel_launch(void* const* d_in, const int* in_sizes, int n_in,
                              void* d_out, int out_size)
{
    const float* x      = (const float*)d_in[0];
    const float* hc1    = (const float*)d_in[2];
    const float* hc2    = (const float*)d_in[3];
    const float* hc3    = (const float*)d_in[4];
    const float* hc4    = (const float*)d_in[5];
    const float* W_i2h  = (const float*)d_in[6];
    const float* b_i2h  = (const float*)d_in[7];
    const float* W_h2h  = (const float*)d_in[8];
    const float* b_h2h  = (const float*)d_in[9];
    const float* W_h2o  = (const float*)d_in[10];
    const float* b_h2o  = (const float*)d_in[11];
    const float* W_fcc  = (const float*)d_in[12];
    const float* b_fcc  = (const float*)d_in[13];
    float* out = (float*)d_out;

    uint32_t *hsHi, *hsLo; float* o64; uint4 *wfrag, *wfragO;
    cudaGetSymbolAddress((void**)&hsHi,   g_hsHi);
    cudaGetSymbolAddress((void**)&hsLo,   g_hsLo);
    cudaGetSymbolAddress((void**)&o64,    g_out64);
    cudaGetSymbolAddress((void**)&wfrag,  g_wfrag);
    cudaGetSymbolAddress((void**)&wfragO, g_wfragO);

    // pass-throughs + weight fragment prep
    copy3_kernel<<<(BH/4)/256, 256>>>(
        (const float4*)hc2, (const float4*)hc3, (const float4*)hc4,
        (float4*)(out + OFF_HC2), (float4*)(out + OFF_HC3), (float4*)(out + OFF_HC4));
    prep_frag<<<64, 256>>>(W_h2h, wfrag, 32);
    prep_frag<<<16, 256>>>(W_h2o, wfragO, 8);

    // i2h_seq = x @ W_i2h^T + b  [131072 x 256], K=64
    sgemm2<128, 128, 8, 8, 0><<<dim3(MROWS/128, HID/128), 256>>>(
        MROWS, HID, IN_F, x, W_i2h, b_i2h, out + OFF_I2H);

    // persistent tensor-core 16-step recurrence (512 threads, barrier-light)
    cudaFuncSetAttribute(rnn_mma,
                         cudaFuncAttributeMaxDynamicSharedMemorySize, RNN_SMEM);
    rnn_mma<<<BATCH/64, 512, RNN_SMEM>>>(
        hc1, wfrag, b_h2h, out + OFF_I2H,
        out + OFF_H2H, hsHi, hsLo, out + OFF_HC1);

    // out64 = tanh(hs @ W_h2o^T + b)  via HMMA on packed bf16 hs
    h2o_mma<<<MROWS/128, 256>>>(hsHi, hsLo, wfragO, b_h2o, o64);

    // output_seq = out64 @ W_fcc^T + b_fcc
    fcc_kernel<<<MROWS/256, 256>>>(o64, W_fcc, b_fcc, out + OFF_OUTSEQ);
}

// round 14
// speedup vs baseline: 3.2915x; 1.0940x over previous
#include <cuda_runtime.h>
#include <cuda_bf16.h>
#include <stdint.h>
#include <math.h>

// ---------------- problem constants ----------------
#define T_STEPS 16
#define BATCH   8192
#define HID     256
#define IN_F    64
#define OUT_F   64
#define NCLS    8
#define MROWS   (T_STEPS*BATCH)
#define BH      (BATCH*HID)

// ---------------- output layout (reference return order, fp32) -------------
#define OFF_OUTSEQ 0
#define LEN_OUTSEQ (T_STEPS*BATCH*NCLS)
#define OFF_HC1    (OFF_OUTSEQ + LEN_OUTSEQ)
#define OFF_HC2    (OFF_HC1 + BH)
#define OFF_HC3    (OFF_HC2 + BH)
#define OFF_HC4    (OFF_HC3 + BH)
#define OFF_I2H    (OFF_HC4 + BH)
#define OFF_H2H    (OFF_I2H + (size_t)T_STEPS*BH)

// ---------------- scratch ----------------
// hidden states as packed bf16 pairs (hi/lo split), [MROWS][128] uint32 each
__device__ uint32_t g_hsHi[(size_t)MROWS * (HID/2)];
__device__ uint32_t g_hsLo[(size_t)MROWS * (HID/2)];
// B-fragment images: [kchunk][ntile][lane] uint4
__device__ uint4 g_wfrag [16 * 32 * 32];   // W_h2h  (K=256, N=256)
__device__ uint4 g_wfragO[16 *  8 * 32];   // W_h2o  (K=256, N=64)
__device__ uint4 g_wfragI[ 4 * 32 * 32];   // W_i2h  (K=64,  N=256)

// ---------------- mma helpers ----------------------------------------------
__device__ __forceinline__ uint32_t smem_u32(const void* p) {
    uint32_t a;
    asm("{ .reg .u64 t; cvta.to.shared.u64 t, %1; cvt.u32.u64 %0, t; }"
        : "=r"(a) : "l"(p));
    return a;
}
__device__ __forceinline__ void ldsm4(uint32_t* r, uint32_t addr) {
    asm volatile("ldmatrix.sync.aligned.m8n8.x4.shared.b16 {%0,%1,%2,%3}, [%4];"
                 : "=r"(r[0]), "=r"(r[1]), "=r"(r[2]), "=r"(r[3]) : "r"(addr));
}
__device__ __forceinline__ void mma16816(float* c, const uint32_t* a,
                                         uint32_t b0, uint32_t b1) {
    asm volatile("mma.sync.aligned.m16n8k16.row.col.f32.bf16.bf16.f32 "
                 "{%0,%1,%2,%3}, {%4,%5,%6,%7}, {%8,%9}, {%0,%1,%2,%3};"
                 : "+f"(c[0]), "+f"(c[1]), "+f"(c[2]), "+f"(c[3])
                 : "r"(a[0]), "r"(a[1]), "r"(a[2]), "r"(a[3]), "r"(b0), "r"(b1));
}
__device__ __forceinline__ uint32_t bfp(float x, float y) {
    __nv_bfloat162 t;
    t.x = __float2bfloat16_rn(x); t.y = __float2bfloat16_rn(y);
    return *reinterpret_cast<uint32_t*>(&t);
}
// split a float2 into packed bf16 hi + residual lo
__device__ __forceinline__ void split2(float2 v, uint32_t& hi, uint32_t& lo) {
    const float hx = __bfloat162float(__float2bfloat16_rn(v.x));
    const float hy = __bfloat162float(__float2bfloat16_rn(v.y));
    hi = bfp(v.x, v.y);
    lo = bfp(v.x - hx, v.y - hy);
}

// ---------------------------------------------------------------------------
// Prep: pack W [N x kdim] fp32 into bf16 hi/lo B-fragments.
// Frag layout [c][j][l]: n = j*8 + l/4, k0 = c*16 + (l%4)*2;
// uint4 = {hi(k0),hi(k0+8),lo(k0),lo(k0+8)}
// ---------------------------------------------------------------------------
__global__ void __launch_bounds__(256)
prep_frag(const float* __restrict__ W, uint4* __restrict__ outF,
          int njt, int kdim)
{
    const int idx = blockIdx.x * 256 + threadIdx.x;
    const int l = idx & 31, g = idx >> 5;
    const int j = g % njt, c = g / njt;
    const int n  = j * 8 + (l >> 2);
    const int k0 = c * 16 + (l & 3) * 2;
    uint4 v;
    split2(*reinterpret_cast<const float2*>(&W[(size_t)n*kdim + k0]),     v.x, v.z);
    split2(*reinterpret_cast<const float2*>(&W[(size_t)n*kdim + k0 + 8]), v.y, v.w);
    outF[(c * njt + j) * 32 + l] = v;
}

// ---------------------------------------------------------------------------
// Persistent tensor-core Elman recurrence. 128 CTAs x 512 thr (16 warps),
// M=64 rows/CTA. A = h in SMEM bf16 hi/lo images (APAD=264 elem stride ->
// conflict-free ldmatrix). B loaded per-warp directly from g_wfrag.
// ---------------------------------------------------------------------------
#define APAD 264
#define SM_ALO (64*APAD)
#define RNN_SMEM (2*64*APAD*2)        // 67,584 B

__global__ void __launch_bounds__(512)
rnn_mma(const float* __restrict__ hc1, const uint4* __restrict__ Wfrag,
        const float* __restrict__ bias, const float* __restrict__ i2h,
        float* __restrict__ h2h_seq,
        uint32_t* __restrict__ hsHi, uint32_t* __restrict__ hsLo,
        float* __restrict__ hc1_out)
{
    extern __shared__ char sm8[];
    __nv_bfloat16* Ahi = (__nv_bfloat16*)sm8;
    __nv_bfloat16* Alo = Ahi + SM_ALO;

    const int tid = threadIdx.x;
    const int l   = tid & 31;
    const int wid = tid >> 5;
    const int wm  = wid & 1;
    const int wn  = wid >> 1;
    const int bm  = blockIdx.x * 64;

    for (int i = tid; i < 64 * 128; i += 512) {
        const int m = i >> 7, kp = (i & 127) * 2;
        uint32_t hi, lo;
        split2(*reinterpret_cast<const float2*>(&hc1[(size_t)(bm+m)*HID + kp]), hi, lo);
        *reinterpret_cast<uint32_t*>(&Ahi[m*APAD + kp]) = hi;
        *reinterpret_cast<uint32_t*>(&Alo[m*APAD + kp]) = lo;
    }

    float2 bias2[4];
#pragma unroll
    for (int nt = 0; nt < 4; nt++)
        bias2[nt] = *reinterpret_cast<const float2*>(&bias[wn*32 + nt*8 + (l&3)*2]);

    const uint32_t aHiBase = smem_u32(Ahi);
    const uint32_t aLoBase = smem_u32(Alo);
    const int mi = l >> 3, rr8 = l & 7;
    const uint32_t ldsmOff = (uint32_t)((((mi & 1) * 8 + rr8) * APAD + (mi >> 1) * 8) * 2);
    const uint4* wbase = Wfrag + (wn * 4) * 32 + l;

    __syncthreads();

#pragma unroll 1
    for (int t = 0; t < T_STEPS; t++) {
        float acc[2][4][4];
#pragma unroll
        for (int a = 0; a < 2; a++)
#pragma unroll
            for (int b = 0; b < 4; b++)
#pragma unroll
                for (int d = 0; d < 4; d++) acc[a][b][d] = 0.0f;

        uint4 bcur[4];
#pragma unroll
        for (int nt = 0; nt < 4; nt++) bcur[nt] = wbase[nt*32];

#pragma unroll 1
        for (int c = 0; c < 16; c++) {
            uint4 bnext[4];
            if (c < 15) {
#pragma unroll
                for (int nt = 0; nt < 4; nt++)
                    bnext[nt] = wbase[(c+1)*1024 + nt*32];
            }
            uint32_t ah[2][4], al[2][4];
#pragma unroll
            for (int mt = 0; mt < 2; mt++) {
                const uint32_t rowByte = (uint32_t)(((wm*32 + mt*16) * APAD + c*16) * 2);
                ldsm4(ah[mt], aHiBase + rowByte + ldsmOff);
                ldsm4(al[mt], aLoBase + rowByte + ldsmOff);
            }
#pragma unroll
            for (int nt = 0; nt < 4; nt++) {
#pragma unroll
                for (int mt = 0; mt < 2; mt++) {
                    mma16816(acc[mt][nt], ah[mt], bcur[nt].x, bcur[nt].y);
                    mma16816(acc[mt][nt], ah[mt], bcur[nt].z, bcur[nt].w);
                    mma16816(acc[mt][nt], al[mt], bcur[nt].x, bcur[nt].y);
                }
            }
#pragma unroll
            for (int nt = 0; nt < 4; nt++) bcur[nt] = bnext[nt];
        }
        __syncthreads();

#pragma unroll
        for (int mt = 0; mt < 2; mt++) {
            const int m0 = wm*32 + mt*16 + (l >> 2);
#pragma unroll
            for (int nt = 0; nt < 4; nt++) {
                const int n = wn*32 + nt*8 + (l & 3)*2;
                const float2 bv = bias2[nt];
#pragma unroll
                for (int rr = 0; rr < 2; rr++) {
                    const int mrel = m0 + rr*8;
                    const float vx = acc[mt][nt][rr*2+0] + bv.x;
                    const float vy = acc[mt][nt][rr*2+1] + bv.y;
                    const size_t gi = ((size_t)t*BATCH + bm + mrel)*HID + n;
                    *reinterpret_cast<float2*>(&h2h_seq[gi]) = make_float2(vx, vy);
                    const float2 xi = *reinterpret_cast<const float2*>(&i2h[gi]);
                    const float h0 = tanhf(xi.x + vx);
                    const float h1 = tanhf(xi.y + vy);
                    uint32_t phi, plo;
                    split2(make_float2(h0, h1), phi, plo);
                    hsHi[gi >> 1] = phi;
                    hsLo[gi >> 1] = plo;
                    if (t == T_STEPS - 1)
                        *reinterpret_cast<float2*>(&hc1_out[(size_t)(bm+mrel)*HID + n])
                            = make_float2(h0, h1);
                    *reinterpret_cast<uint32_t*>(&Ahi[mrel*APAD + n]) = phi;
                    *reinterpret_cast<uint32_t*>(&Alo[mrel*APAD + n]) = plo;
                }
            }
        }
        __syncthreads();
    }
}

// ---------------------------------------------------------------------------
// h2o + fcc fused HMMA kernel: out8 = tanh(hs @ W_h2o^T + b_h2o) @ W_fcc^T + b_fcc
// 1024 CTAs x 256 thr. A from packed bf16 hi/lo hs. Warp: 16 rows x 64 cols.
// fcc done per-lane (16-col partial dots) + quad shfl reduction.
// ---------------------------------------------------------------------------
__global__ void __launch_bounds__(256)
h2o_mma(const uint32_t* __restrict__ Hhi, const uint32_t* __restrict__ Hlo,
        const uint4* __restrict__ WfragO, const float* __restrict__ bias,
        const float* __restrict__ Wfcc, const float* __restrict__ bfcc,
        float* __restrict__ out8)
{
    __shared__ float Ws[NCLS * OUT_F];
    __shared__ float bs[NCLS];

    const int tid = threadIdx.x;
    const int l   = tid & 31;
    const int wid = tid >> 5;
    const int bm  = blockIdx.x * 128;

    for (int i = tid; i < NCLS * OUT_F; i += 256) Ws[i] = Wfcc[i];
    if (tid < NCLS) bs[tid] = bfcc[tid];

    float acc[8][4];
#pragma unroll
    for (int b = 0; b < 8; b++)
#pragma unroll
        for (int d = 0; d < 4; d++) acc[b][d] = 0.0f;

    const int row0 = bm + wid*16 + (l >> 2);
    const size_t r0b = (size_t)row0 * (HID/2);
    const size_t r1b = r0b + 8 * (HID/2);
    const int kb = (l & 3);
    const uint4* wb = WfragO + l;

#pragma unroll 1
    for (int c = 0; c < 16; c++) {
        uint32_t ah[4], al[4];
        const int base = c*8 + kb;
        ah[0] = Hhi[r0b + base];   ah[1] = Hhi[r1b + base];
        ah[2] = Hhi[r0b + base+4]; ah[3] = Hhi[r1b + base+4];
        al[0] = Hlo[r0b + base];   al[1] = Hlo[r1b + base];
        al[2] = Hlo[r0b + base+4]; al[3] = Hlo[r1b + base+4];
#pragma unroll
        for (int nt = 0; nt < 8; nt++) {
            const uint4 b = wb[(c*8 + nt)*32];
            mma16816(acc[nt], ah, b.x, b.y);
            mma16816(acc[nt], ah, b.z, b.w);
            mma16816(acc[nt], al, b.x, b.y);
        }
    }
    __syncthreads();   // Ws/bs visible (loaded before the long mma loop)

    // tanh epilogue -> v[rr][nt][2]
    float v[2][8][2];
#pragma unroll
    for (int nt = 0; nt < 8; nt++) {
        const int n = nt*8 + (l & 3)*2;
        const float2 bv = *reinterpret_cast<const float2*>(&bias[n]);
#pragma unroll
        for (int rr = 0; rr < 2; rr++) {
            v[rr][nt][0] = tanhf(acc[nt][rr*2+0] + bv.x);
            v[rr][nt][1] = tanhf(acc[nt][rr*2+1] + bv.y);
        }
    }

    // fused fcc: per-lane partial dot over its 16 cols, reduce across quad
    const float2* Ws2 = reinterpret_cast<const float2*>(Ws);
    float p0[NCLS], p1[NCLS];
#pragma unroll
    for (int cls = 0; cls < NCLS; cls++) {
        float a0 = 0.0f, a1 = 0.0f;
#pragma unroll
        for (int nt = 0; nt < 8; nt++) {
            const float2 w = Ws2[cls*32 + nt*4 + (l & 3)];
            a0 += v[0][nt][0]*w.x + v[0][nt][1]*w.y;
            a1 += v[1][nt][0]*w.x + v[1][nt][1]*w.y;
        }
        a0 += __shfl_xor_sync(0xffffffffu, a0, 1);
        a0 += __shfl_xor_sync(0xffffffffu, a0, 2);
        a1 += __shfl_xor_sync(0xffffffffu, a1, 1);
        a1 += __shfl_xor_sync(0xffffffffu, a1, 2);
        p0[cls] = a0 + bs[cls];
        p1[cls] = a1 + bs[cls];
    }
    if ((l & 3) == 0) {
        const size_t r0 = (size_t)row0 * NCLS;
        const size_t r1 = (size_t)(row0 + 8) * NCLS;
        *reinterpret_cast<float4*>(&out8[r0])     = make_float4(p0[0], p0[1], p0[2], p0[3]);
        *reinterpret_cast<float4*>(&out8[r0 + 4]) = make_float4(p0[4], p0[5], p0[6], p0[7]);
        *reinterpret_cast<float4*>(&out8[r1])     = make_float4(p1[0], p1[1], p1[2], p1[3]);
        *reinterpret_cast<float4*>(&out8[r1 + 4]) = make_float4(p1[4], p1[5], p1[6], p1[7]);
    }
}

// ---------------------------------------------------------------------------
// i2h HMMA kernel: i2h = x @ W_i2h^T + b.  1024 CTAs x 512 thr (16 warps).
// x split to bf16 hi/lo in registers at load. Block 128 rows x 256 cols;
// warp tile 32m x 64n (warps: 4m x 4n). K=64 -> 4 chunks.
// ---------------------------------------------------------------------------
__global__ void __launch_bounds__(512)
i2h_mma(const float* __restrict__ x, const uint4* __restrict__ WfragI,
        const float* __restrict__ bias, float* __restrict__ C)
{
    const int tid = threadIdx.x;
    const int l   = tid & 31;
    const int wid = tid >> 5;
    const int wm  = wid & 3;        // 4 m-groups of 32 rows
    const int wn  = wid >> 2;       // 4 n-groups of 64 cols
    const int bm  = blockIdx.x * 128;

    float2 bias2[8];
#pragma unroll
    for (int nt = 0; nt < 8; nt++)
        bias2[nt] = *reinterpret_cast<const float2*>(&bias[wn*64 + nt*8 + (l&3)*2]);

    float acc[2][8][4];
#pragma unroll
    for (int a = 0; a < 2; a++)
#pragma unroll
        for (int b = 0; b < 8; b++)
#pragma unroll
            for (int d = 0; d < 4; d++) acc[a][b][d] = 0.0f;

#pragma unroll
    for (int c = 0; c < 4; c++) {
        uint32_t ah[2][4], al[2][4];
        const int k0 = c*16 + (l & 3)*2;
#pragma unroll
        for (int mt = 0; mt < 2; mt++) {
            const int r = bm + wm*32 + mt*16 + (l >> 2);
            const float* xr = x + (size_t)r * IN_F;
            split2(*reinterpret_cast<const float2*>(xr + k0),            ah[mt][0], al[mt][0]);
            split2(*reinterpret_cast<const float2*>(xr + 8*IN_F + k0),   ah[mt][1], al[mt][1]);
            split2(*reinterpret_cast<const float2*>(xr + k0 + 8),        ah[mt][2], al[mt][2]);
            split2(*reinterpret_cast<const float2*>(xr + 8*IN_F + k0+8), ah[mt][3], al[mt][3]);
        }
#pragma unroll
        for (int nt = 0; nt < 8; nt++) {
            const uint4 b = WfragI[((c*32) + wn*8 + nt)*32 + l];
#pragma unroll
            for (int mt = 0; mt < 2; mt++) {
                mma16816(acc[mt][nt], ah[mt], b.x, b.y);
                mma16816(acc[mt][nt], ah[mt], b.z, b.w);
                mma16816(acc[mt][nt], al[mt], b.x, b.y);
            }
        }
    }

    // epilogue: bias + store fp32
#pragma unroll
    for (int mt = 0; mt < 2; mt++) {
        const int m0 = bm + wm*32 + mt*16 + (l >> 2);
#pragma unroll
        for (int nt = 0; nt < 8; nt++) {
            const int n = wn*64 + nt*8 + (l & 3)*2;
            const float2 bv = bias2[nt];
#pragma unroll
            for (int rr = 0; rr < 2; rr++) {
                const size_t gi = (size_t)(m0 + rr*8) * HID + n;
                *reinterpret_cast<float2*>(&C[gi]) =
                    make_float2(acc[mt][nt][rr*2+0] + bv.x,
                                acc[mt][nt][rr*2+1] + bv.y);
            }
        }
    }
}

// ---------------------------------------------------------------------------
__global__ void __launch_bounds__(256)
copy3_kernel(const float4* __restrict__ a, const float4* __restrict__ b,
             const float4* __restrict__ c,
             float4* __restrict__ oa, float4* __restrict__ ob,
             float4* __restrict__ oc)
{
    const size_t i = (size_t)blockIdx.x * blockDim.x + threadIdx.x;
    oa[i] = a[i]; ob[i] = b[i]; oc[i] = c[i];
}

// ---------------------------------------------------------------------------
extern "C" void kernel_launch(void* const* d_in, const int* in_sizes, int n_in,
                              void* d_out, int out_size)
{
    const float* x      = (const float*)d_in[0];
    const float* hc1    = (const float*)d_in[2];
    const float* hc2    = (const float*)d_in[3];
    const float* hc3    = (const float*)d_in[4];
    const float* hc4    = (const float*)d_in[5];
    const float* W_i2h  = (const float*)d_in[6];
    const float* b_i2h  = (const float*)d_in[7];
    const float* W_h2h  = (const float*)d_in[8];
    const float* b_h2h  = (const float*)d_in[9];
    const float* W_h2o  = (const float*)d_in[10];
    const float* b_h2o  = (const float*)d_in[11];
    const float* W_fcc  = (const float*)d_in[12];
    const float* b_fcc  = (const float*)d_in[13];
    float* out = (float*)d_out;

    uint32_t *hsHi, *hsLo; uint4 *wfrag, *wfragO, *wfragI;
    cudaGetSymbolAddress((void**)&hsHi,   g_hsHi);
    cudaGetSymbolAddress((void**)&hsLo,   g_hsLo);
    cudaGetSymbolAddress((void**)&wfrag,  g_wfrag);
    cudaGetSymbolAddress((void**)&wfragO, g_wfragO);
    cudaGetSymbolAddress((void**)&wfragI, g_wfragI);

    // pass-throughs + weight fragment prep
    copy3_kernel<<<(BH/4)/256, 256>>>(
        (const float4*)hc2, (const float4*)hc3, (const float4*)hc4,
        (float4*)(out + OFF_HC2), (float4*)(out + OFF_HC3), (float4*)(out + OFF_HC4));
    prep_frag<<<64, 256>>>(W_h2h, wfrag, 32, 256);
    prep_frag<<<16, 256>>>(W_h2o, wfragO, 8, 256);
    prep_frag<<<16, 256>>>(W_i2h, wfragI, 32, 64);

    // i2h_seq = x @ W_i2h^T + b  via HMMA
    i2h_mma<<<MROWS/128, 512>>>(x, wfragI, b_i2h, out + OFF_I2H);

    // persistent tensor-core 16-step recurrence
    cudaFuncSetAttribute(rnn_mma,
                         cudaFuncAttributeMaxDynamicSharedMemorySize, RNN_SMEM);
    rnn_mma<<<BATCH/64, 512, RNN_SMEM>>>(
        hc1, wfrag, b_h2h, out + OFF_I2H,
        out + OFF_H2H, hsHi, hsLo, out + OFF_HC1);

    // output_seq = fcc(tanh(hs @ W_h2o^T + b))  -- h2o + fcc fused
    h2o_mma<<<MROWS/128, 256>>>(hsHi, hsLo, wfragO, b_h2o,
                                W_fcc, b_fcc, out + OFF_OUTSEQ);
}

// round 15
// speedup vs baseline: 3.3578x; 1.0201x over previous
#include <cuda_runtime.h>
#include <cuda_bf16.h>
#include <stdint.h>
#include <math.h>

// ---------------- problem constants ----------------
#define T_STEPS 16
#define BATCH   8192
#define HID     256
#define IN_F    64
#define OUT_F   64
#define NCLS    8
#define MROWS   (T_STEPS*BATCH)
#define BH      (BATCH*HID)

// ---------------- output layout (reference return order, fp32) -------------
#define OFF_OUTSEQ 0
#define LEN_OUTSEQ (T_STEPS*BATCH*NCLS)
#define OFF_HC1    (OFF_OUTSEQ + LEN_OUTSEQ)
#define OFF_HC2    (OFF_HC1 + BH)
#define OFF_HC3    (OFF_HC2 + BH)
#define OFF_HC4    (OFF_HC3 + BH)
#define OFF_I2H    (OFF_HC4 + BH)
#define OFF_H2H    (OFF_I2H + (size_t)T_STEPS*BH)

// ---------------- scratch ----------------
__device__ uint32_t g_hsHi[(size_t)MROWS * (HID/2)];
__device__ uint32_t g_hsLo[(size_t)MROWS * (HID/2)];
// B-fragment images: [kchunk][ntile][lane] uint4
__device__ uint4 g_wfrag [16 * 32 * 32];   // W_h2h  (K=256, N=256)
__device__ uint4 g_wfragO[16 *  8 * 32];   // W_h2o  (K=256, N=64)
__device__ uint4 g_wfragI[ 4 * 32 * 32];   // W_i2h  (K=64,  N=256)

// ---------------- mma helpers ----------------------------------------------
__device__ __forceinline__ uint32_t smem_u32(const void* p) {
    uint32_t a;
    asm("{ .reg .u64 t; cvta.to.shared.u64 t, %1; cvt.u32.u64 %0, t; }"
        : "=r"(a) : "l"(p));
    return a;
}
__device__ __forceinline__ void ldsm4(uint32_t* r, uint32_t addr) {
    asm volatile("ldmatrix.sync.aligned.m8n8.x4.shared.b16 {%0,%1,%2,%3}, [%4];"
                 : "=r"(r[0]), "=r"(r[1]), "=r"(r[2]), "=r"(r[3]) : "r"(addr));
}
__device__ __forceinline__ void mma16816(float* c, const uint32_t* a,
                                         uint32_t b0, uint32_t b1) {
    asm volatile("mma.sync.aligned.m16n8k16.row.col.f32.bf16.bf16.f32 "
                 "{%0,%1,%2,%3}, {%4,%5,%6,%7}, {%8,%9}, {%0,%1,%2,%3};"
                 : "+f"(c[0]), "+f"(c[1]), "+f"(c[2]), "+f"(c[3])
                 : "r"(a[0]), "r"(a[1]), "r"(a[2]), "r"(a[3]), "r"(b0), "r"(b1));
}
__device__ __forceinline__ uint32_t bfp(float x, float y) {
    __nv_bfloat162 t;
    t.x = __float2bfloat16_rn(x); t.y = __float2bfloat16_rn(y);
    return *reinterpret_cast<uint32_t*>(&t);
}
__device__ __forceinline__ void split2(float2 v, uint32_t& hi, uint32_t& lo) {
    const float hx = __bfloat162float(__float2bfloat16_rn(v.x));
    const float hy = __bfloat162float(__float2bfloat16_rn(v.y));
    hi = bfp(v.x, v.y);
    lo = bfp(v.x - hx, v.y - hy);
}
// 16-byte async copy: global -> shared (per-thread; producer == consumer)
__device__ __forceinline__ void cpa16(uint32_t saddr, const void* gptr) {
    asm volatile("cp.async.cg.shared.global [%0], [%1], 16;"
                 :: "r"(saddr), "l"(gptr) : "memory");
}
#define CPA_COMMIT() asm volatile("cp.async.commit_group;" ::: "memory")
#define CPA_WAIT(n)  asm volatile("cp.async.wait_group %0;" :: "n"(n) : "memory")

// ---------------------------------------------------------------------------
// Prep: pack W [N x kdim] fp32 into bf16 hi/lo B-fragments.
// Frag layout [c][j][l]: n = j*8 + l/4, k0 = c*16 + (l%4)*2;
// uint4 = {hi(k0),hi(k0+8),lo(k0),lo(k0+8)}
// ---------------------------------------------------------------------------
__global__ void __launch_bounds__(256)
prep_frag(const float* __restrict__ W, uint4* __restrict__ outF,
          int njt, int kdim)
{
    const int idx = blockIdx.x * 256 + threadIdx.x;
    const int l = idx & 31, g = idx >> 5;
    const int j = g % njt, c = g / njt;
    const int n  = j * 8 + (l >> 2);
    const int k0 = c * 16 + (l & 3) * 2;
    uint4 v;
    split2(*reinterpret_cast<const float2*>(&W[(size_t)n*kdim + k0]),     v.x, v.z);
    split2(*reinterpret_cast<const float2*>(&W[(size_t)n*kdim + k0 + 8]), v.y, v.w);
    outF[(c * njt + j) * 32 + l] = v;
}

// ---------------------------------------------------------------------------
// Persistent tensor-core Elman recurrence. 128 CTAs x 512 thr (16 warps),
// M=64 rows/CTA. A = h in SMEM bf16 hi/lo images (APAD=264 elem stride).
// B streamed per-warp into a private 4-slot SMEM ring via cp.async with
// 3-chunk lookahead (covers L2 latency); ring rolls continuously across
// steps since W is step-invariant. Warp tile 32m x 32n.
// ---------------------------------------------------------------------------
#define APAD 264
#define SM_ALO (64*APAD)
#define SM_BST (2*64*APAD*2)                  // byte offset of B ring (67,584)
#define BWARP_BYTES (4*4*32*16)               // 4 slots x 4 nt x 32 lanes x 16B = 8192
#define RNN_SMEM (SM_BST + 16*BWARP_BYTES)    // 67,584 + 131,072 = 198,656 B

__global__ void __launch_bounds__(512)
rnn_mma(const float* __restrict__ hc1, const uint4* __restrict__ Wfrag,
        const float* __restrict__ bias, const float* __restrict__ i2h,
        float* __restrict__ h2h_seq,
        uint32_t* __restrict__ hsHi, uint32_t* __restrict__ hsLo,
        float* __restrict__ hc1_out)
{
    extern __shared__ char sm8[];
    __nv_bfloat16* Ahi = (__nv_bfloat16*)sm8;
    __nv_bfloat16* Alo = Ahi + SM_ALO;

    const int tid = threadIdx.x;
    const int l   = tid & 31;
    const int wid = tid >> 5;
    const int wm  = wid & 1;
    const int wn  = wid >> 1;
    const int bm  = blockIdx.x * 64;

    // prologue: split hc1 rows into Ahi/Alo
    for (int i = tid; i < 64 * 128; i += 512) {
        const int m = i >> 7, kp = (i & 127) * 2;
        uint32_t hi, lo;
        split2(*reinterpret_cast<const float2*>(&hc1[(size_t)(bm+m)*HID + kp]), hi, lo);
        *reinterpret_cast<uint32_t*>(&Ahi[m*APAD + kp]) = hi;
        *reinterpret_cast<uint32_t*>(&Alo[m*APAD + kp]) = lo;
    }

    float2 bias2[4];
#pragma unroll
    for (int nt = 0; nt < 4; nt++)
        bias2[nt] = *reinterpret_cast<const float2*>(&bias[wn*32 + nt*8 + (l&3)*2]);

    const uint32_t aHiBase = smem_u32(Ahi);
    const uint32_t aLoBase = smem_u32(Alo);
    const int mi = l >> 3, rr8 = l & 7;
    const uint32_t ldsmOff = (uint32_t)((((mi & 1) * 8 + rr8) * APAD + (mi >> 1) * 8) * 2);

    // B ring: per-warp region; lane-private 16B cells
    const uint4* wbase = Wfrag + (wn * 4) * 32 + l;        // + c*1024 + nt*32
    uint4* BwBase = (uint4*)(sm8 + SM_BST) + wid * 512;    // 512 uint4 per warp
    const uint32_t bStLane = smem_u32(BwBase) + (uint32_t)l * 16;

    // issue chunks 0..2 (3 groups in flight)
#pragma unroll
    for (int p = 0; p < 3; p++) {
#pragma unroll
        for (int nt = 0; nt < 4; nt++)
            cpa16(bStLane + (uint32_t)(p*2048 + nt*512), wbase + p*1024 + nt*32);
        CPA_COMMIT();
    }

    __syncthreads();

#pragma unroll 1
    for (int t = 0; t < T_STEPS; t++) {
        float acc[2][4][4];
#pragma unroll
        for (int a = 0; a < 2; a++)
#pragma unroll
            for (int b = 0; b < 4; b++)
#pragma unroll
                for (int d = 0; d < 4; d++) acc[a][b][d] = 0.0f;

#pragma unroll 1
        for (int c = 0; c < 16; c++) {
            // issue chunk (c+3) mod 16 into slot (c+3)&3 (rolls into next step)
            {
                const int cn = (c + 3) & 15;
                const int sl = (c + 3) & 3;
#pragma unroll
                for (int nt = 0; nt < 4; nt++)
                    cpa16(bStLane + (uint32_t)(sl*2048 + nt*512),
                          wbase + cn*1024 + nt*32);
                CPA_COMMIT();
            }
            CPA_WAIT(3);   // chunk c resident (issued 3 groups ago)

            const uint4* slot = BwBase + (c & 3) * 128 + l;
            uint4 bcur[4];
#pragma unroll
            for (int nt = 0; nt < 4; nt++) bcur[nt] = slot[nt*32];

            uint32_t ah[2][4], al[2][4];
#pragma unroll
            for (int mt = 0; mt < 2; mt++) {
                const uint32_t rowByte = (uint32_t)(((wm*32 + mt*16) * APAD + c*16) * 2);
                ldsm4(ah[mt], aHiBase + rowByte + ldsmOff);
                ldsm4(al[mt], aLoBase + rowByte + ldsmOff);
            }
#pragma unroll
            for (int nt = 0; nt < 4; nt++) {
#pragma unroll
                for (int mt = 0; mt < 2; mt++) {
                    mma16816(acc[mt][nt], ah[mt], bcur[nt].x, bcur[nt].y);
                    mma16816(acc[mt][nt], ah[mt], bcur[nt].z, bcur[nt].w);
                    mma16816(acc[mt][nt], al[mt], bcur[nt].x, bcur[nt].y);
                }
            }
        }
        __syncthreads();   // all A reads of this step done

        // epilogue
#pragma unroll
        for (int mt = 0; mt < 2; mt++) {
            const int m0 = wm*32 + mt*16 + (l >> 2);
#pragma unroll
            for (int nt = 0; nt < 4; nt++) {
                const int n = wn*32 + nt*8 + (l & 3)*2;
                const float2 bv = bias2[nt];
#pragma unroll
                for (int rr = 0; rr < 2; rr++) {
                    const int mrel = m0 + rr*8;
                    const float vx = acc[mt][nt][rr*2+0] + bv.x;
                    const float vy = acc[mt][nt][rr*2+1] + bv.y;
                    const size_t gi = ((size_t)t*BATCH + bm + mrel)*HID + n;
                    *reinterpret_cast<float2*>(&h2h_seq[gi]) = make_float2(vx, vy);
                    const float2 xi = *reinterpret_cast<const float2*>(&i2h[gi]);
                    const float h0 = tanhf(xi.x + vx);
                    const float h1 = tanhf(xi.y + vy);
                    uint32_t phi, plo;
                    split2(make_float2(h0, h1), phi, plo);
                    hsHi[gi >> 1] = phi;
                    hsLo[gi >> 1] = plo;
                    if (t == T_STEPS - 1)
                        *reinterpret_cast<float2*>(&hc1_out[(size_t)(bm+mrel)*HID + n])
                            = make_float2(h0, h1);
                    *reinterpret_cast<uint32_t*>(&Ahi[mrel*APAD + n]) = phi;
                    *reinterpret_cast<uint32_t*>(&Alo[mrel*APAD + n]) = plo;
                }
            }
        }
        __syncthreads();   // A updated before next step's ldmatrix
    }
}

// ---------------------------------------------------------------------------
// h2o + fcc fused HMMA kernel: out8 = tanh(hs @ W_h2o^T + b_h2o) @ W_fcc^T + b_fcc
// ---------------------------------------------------------------------------
__global__ void __launch_bounds__(256)
h2o_mma(const uint32_t* __restrict__ Hhi, const uint32_t* __restrict__ Hlo,
        const uint4* __restrict__ WfragO, const float* __restrict__ bias,
        const float* __restrict__ Wfcc, const float* __restrict__ bfcc,
        float* __restrict__ out8)
{
    __shared__ float Ws[NCLS * OUT_F];
    __shared__ float bs[NCLS];

    const int tid = threadIdx.x;
    const int l   = tid & 31;
    const int wid = tid >> 5;
    const int bm  = blockIdx.x * 128;

    for (int i = tid; i < NCLS * OUT_F; i += 256) Ws[i] = Wfcc[i];
    if (tid < NCLS) bs[tid] = bfcc[tid];

    float acc[8][4];
#pragma unroll
    for (int b = 0; b < 8; b++)
#pragma unroll
        for (int d = 0; d < 4; d++) acc[b][d] = 0.0f;

    const int row0 = bm + wid*16 + (l >> 2);
    const size_t r0b = (size_t)row0 * (HID/2);
    const size_t r1b = r0b + 8 * (HID/2);
    const int kb = (l & 3);
    const uint4* wb = WfragO + l;

#pragma unroll 1
    for (int c = 0; c < 16; c++) {
        uint32_t ah[4], al[4];
        const int base = c*8 + kb;
        ah[0] = Hhi[r0b + base];   ah[1] = Hhi[r1b + base];
        ah[2] = Hhi[r0b + base+4]; ah[3] = Hhi[r1b + base+4];
        al[0] = Hlo[r0b + base];   al[1] = Hlo[r1b + base];
        al[2] = Hlo[r0b + base+4]; al[3] = Hlo[r1b + base+4];
#pragma unroll
        for (int nt = 0; nt < 8; nt++) {
            const uint4 b = wb[(c*8 + nt)*32];
            mma16816(acc[nt], ah, b.x, b.y);
            mma16816(acc[nt], ah, b.z, b.w);
            mma16816(acc[nt], al, b.x, b.y);
        }
    }
    __syncthreads();   // Ws/bs visible

    float v[2][8][2];
#pragma unroll
    for (int nt = 0; nt < 8; nt++) {
        const int n = nt*8 + (l & 3)*2;
        const float2 bv = *reinterpret_cast<const float2*>(&bias[n]);
#pragma unroll
        for (int rr = 0; rr < 2; rr++) {
            v[rr][nt][0] = tanhf(acc[nt][rr*2+0] + bv.x);
            v[rr][nt][1] = tanhf(acc[nt][rr*2+1] + bv.y);
        }
    }

    const float2* Ws2 = reinterpret_cast<const float2*>(Ws);
    float p0[NCLS], p1[NCLS];
#pragma unroll
    for (int cls = 0; cls < NCLS; cls++) {
        float a0 = 0.0f, a1 = 0.0f;
#pragma unroll
        for (int nt = 0; nt < 8; nt++) {
            const float2 w = Ws2[cls*32 + nt*4 + (l & 3)];
            a0 += v[0][nt][0]*w.x + v[0][nt][1]*w.y;
            a1 += v[1][nt][0]*w.x + v[1][nt][1]*w.y;
        }
        a0 += __shfl_xor_sync(0xffffffffu, a0, 1);
        a0 += __shfl_xor_sync(0xffffffffu, a0, 2);
        a1 += __shfl_xor_sync(0xffffffffu, a1, 1);
        a1 += __shfl_xor_sync(0xffffffffu, a1, 2);
        p0[cls] = a0 + bs[cls];
        p1[cls] = a1 + bs[cls];
    }
    if ((l & 3) == 0) {
        const size_t r0 = (size_t)row0 * NCLS;
        const size_t r1 = (size_t)(row0 + 8) * NCLS;
        *reinterpret_cast<float4*>(&out8[r0])     = make_float4(p0[0], p0[1], p0[2], p0[3]);
        *reinterpret_cast<float4*>(&out8[r0 + 4]) = make_float4(p0[4], p0[5], p0[6], p0[7]);
        *reinterpret_cast<float4*>(&out8[r1])     = make_float4(p1[0], p1[1], p1[2], p1[3]);
        *reinterpret_cast<float4*>(&out8[r1 + 4]) = make_float4(p1[4], p1[5], p1[6], p1[7]);
    }
}

// ---------------------------------------------------------------------------
// i2h HMMA kernel: i2h = x @ W_i2h^T + b.
// ---------------------------------------------------------------------------
__global__ void __launch_bounds__(512)
i2h_mma(const float* __restrict__ x, const uint4* __restrict__ WfragI,
        const float* __restrict__ bias, float* __restrict__ C)
{
    const int tid = threadIdx.x;
    const int l   = tid & 31;
    const int wid = tid >> 5;
    const int wm  = wid & 3;
    const int wn  = wid >> 2;
    const int bm  = blockIdx.x * 128;

    float2 bias2[8];
#pragma unroll
    for (int nt = 0; nt < 8; nt++)
        bias2[nt] = *reinterpret_cast<const float2*>(&bias[wn*64 + nt*8 + (l&3)*2]);

    float acc[2][8][4];
#pragma unroll
    for (int a = 0; a < 2; a++)
#pragma unroll
        for (int b = 0; b < 8; b++)
#pragma unroll
            for (int d = 0; d < 4; d++) acc[a][b][d] = 0.0f;

#pragma unroll
    for (int c = 0; c < 4; c++) {
        uint32_t ah[2][4], al[2][4];
        const int k0 = c*16 + (l & 3)*2;
#pragma unroll
        for (int mt = 0; mt < 2; mt++) {
            const int r = bm + wm*32 + mt*16 + (l >> 2);
            const float* xr = x + (size_t)r * IN_F;
            split2(*reinterpret_cast<const float2*>(xr + k0),            ah[mt][0], al[mt][0]);
            split2(*reinterpret_cast<const float2*>(xr + 8*IN_F + k0),   ah[mt][1], al[mt][1]);
            split2(*reinterpret_cast<const float2*>(xr + k0 + 8),        ah[mt][2], al[mt][2]);
            split2(*reinterpret_cast<const float2*>(xr + 8*IN_F + k0+8), ah[mt][3], al[mt][3]);
        }
#pragma unroll
        for (int nt = 0; nt < 8; nt++) {
            const uint4 b = WfragI[((c*32) + wn*8 + nt)*32 + l];
#pragma unroll
            for (int mt = 0; mt < 2; mt++) {
                mma16816(acc[mt][nt], ah[mt], b.x, b.y);
                mma16816(acc[mt][nt], ah[mt], b.z, b.w);
                mma16816(acc[mt][nt], al[mt], b.x, b.y);
            }
        }
    }

#pragma unroll
    for (int mt = 0; mt < 2; mt++) {
        const int m0 = bm + wm*32 + mt*16 + (l >> 2);
#pragma unroll
        for (int nt = 0; nt < 8; nt++) {
            const int n = wn*64 + nt*8 + (l & 3)*2;
            const float2 bv = bias2[nt];
#pragma unroll
            for (int rr = 0; rr < 2; rr++) {
                const size_t gi = (size_t)(m0 + rr*8) * HID + n;
                *reinterpret_cast<float2*>(&C[gi]) =
                    make_float2(acc[mt][nt][rr*2+0] + bv.x,
                                acc[mt][nt][rr*2+1] + bv.y);
            }
        }
    }
}

// ---------------------------------------------------------------------------
__global__ void __launch_bounds__(256)
copy3_kernel(const float4* __restrict__ a, const float4* __restrict__ b,
             const float4* __restrict__ c,
             float4* __restrict__ oa, float4* __restrict__ ob,
             float4* __restrict__ oc)
{
    const size_t i = (size_t)blockIdx.x * blockDim.x + threadIdx.x;
    oa[i] = a[i]; ob[i] = b[i]; oc[i] = c[i];
}

// ---------------------------------------------------------------------------
extern "C" void kernel_launch(void* const* d_in, const int* in_sizes, int n_in,
                              void* d_out, int out_size)
{
    const float* x      = (const float*)d_in[0];
    const float* hc1    = (const float*)d_in[2];
    const float* hc2    = (const float*)d_in[3];
    const float* hc3    = (const float*)d_in[4];
    const float* hc4    = (const float*)d_in[5];
    const float* W_i2h  = (const float*)d_in[6];
    const float* b_i2h  = (const float*)d_in[7];
    const float* W_h2h  = (const float*)d_in[8];
    const float* b_h2h  = (const float*)d_in[9];
    const float* W_h2o  = (const float*)d_in[10];
    const float* b_h2o  = (const float*)d_in[11];
    const float* W_fcc  = (const float*)d_in[12];
    const float* b_fcc  = (const float*)d_in[13];
    float* out = (float*)d_out;

    uint32_t *hsHi, *hsLo; uint4 *wfrag, *wfragO, *wfragI;
    cudaGetSymbolAddress((void**)&hsHi,   g_hsHi);
    cudaGetSymbolAddress((void**)&hsLo,   g_hsLo);
    cudaGetSymbolAddress((void**)&wfrag,  g_wfrag);
    cudaGetSymbolAddress((void**)&wfragO, g_wfragO);
    cudaGetSymbolAddress((void**)&wfragI, g_wfragI);

    // pass-throughs + weight fragment prep
    copy3_kernel<<<(BH/4)/256, 256>>>(
        (const float4*)hc2, (const float4*)hc3, (const float4*)hc4,
        (float4*)(out + OFF_HC2), (float4*)(out + OFF_HC3), (float4*)(out + OFF_HC4));
    prep_frag<<<64, 256>>>(W_h2h, wfrag, 32, 256);
    prep_frag<<<16, 256>>>(W_h2o, wfragO, 8, 256);
    prep_frag<<<16, 256>>>(W_i2h, wfragI, 32, 64);

    // i2h_seq = x @ W_i2h^T + b  via HMMA
    i2h_mma<<<MROWS/128, 512>>>(x, wfragI, b_i2h, out + OFF_I2H);

    // persistent tensor-core 16-step recurrence (cp.async deep B prefetch)
    cudaFuncSetAttribute(rnn_mma,
                         cudaFuncAttributeMaxDynamicSharedMemorySize, RNN_SMEM);
    rnn_mma<<<BATCH/64, 512, RNN_SMEM>>>(
        hc1, wfrag, b_h2h, out + OFF_I2H,
        out + OFF_H2H, hsHi, hsLo, out + OFF_HC1);

    // output_seq = fcc(tanh(hs @ W_h2o^T + b))  -- h2o + fcc fused
    h2o_mma<<<MROWS/128, 256>>>(hsHi, hsLo, wfragO, b_h2o,
                                W_fcc, b_fcc, out + OFF_OUTSEQ);
}

// round 17
// speedup vs baseline: 3.3855x; 1.0083x over previous
#include <cuda_runtime.h>
#include <cuda_bf16.h>
#include <stdint.h>
#include <math.h>

// ---------------- problem constants ----------------
#define T_STEPS 16
#define BATCH   8192
#define HID     256
#define IN_F    64
#define OUT_F   64
#define NCLS    8
#define MROWS   (T_STEPS*BATCH)
#define BH      (BATCH*HID)

// ---------------- output layout (reference return order, fp32) -------------
#define OFF_OUTSEQ 0
#define LEN_OUTSEQ (T_STEPS*BATCH*NCLS)
#define OFF_HC1    (OFF_OUTSEQ + LEN_OUTSEQ)
#define OFF_HC2    (OFF_HC1 + BH)
#define OFF_HC3    (OFF_HC2 + BH)
#define OFF_HC4    (OFF_HC3 + BH)
#define OFF_I2H    (OFF_HC4 + BH)
#define OFF_H2H    (OFF_I2H + (size_t)T_STEPS*BH)

// ---------------- scratch ----------------
__device__ uint32_t g_hsHi[(size_t)MROWS * (HID/2)];
__device__ uint32_t g_hsLo[(size_t)MROWS * (HID/2)];
// B-fragment images: [kchunk][ntile][lane] uint4
__device__ uint4 g_wfrag [16 * 32 * 32];   // W_h2h  (K=256, N=256)
__device__ uint4 g_wfragO[16 *  8 * 32];   // W_h2o  (K=256, N=64)
__device__ uint4 g_wfragI[ 4 * 32 * 32];   // W_i2h  (K=64,  N=256)

// ---------------- mma helpers ----------------------------------------------
__device__ __forceinline__ uint32_t smem_u32(const void* p) {
    uint32_t a;
    asm("{ .reg .u64 t; cvta.to.shared.u64 t, %1; cvt.u32.u64 %0, t; }"
        : "=r"(a) : "l"(p));
    return a;
}
__device__ __forceinline__ void ldsm4(uint32_t* r, uint32_t addr) {
    asm volatile("ldmatrix.sync.aligned.m8n8.x4.shared.b16 {%0,%1,%2,%3}, [%4];"
                 : "=r"(r[0]), "=r"(r[1]), "=r"(r[2]), "=r"(r[3]) : "r"(addr));
}
__device__ __forceinline__ void mma16816(float* c, const uint32_t* a,
                                         uint32_t b0, uint32_t b1) {
    asm volatile("mma.sync.aligned.m16n8k16.row.col.f32.bf16.bf16.f32 "
                 "{%0,%1,%2,%3}, {%4,%5,%6,%7}, {%8,%9}, {%0,%1,%2,%3};"
                 : "+f"(c[0]), "+f"(c[1]), "+f"(c[2]), "+f"(c[3])
                 : "r"(a[0]), "r"(a[1]), "r"(a[2]), "r"(a[3]), "r"(b0), "r"(b1));
}
__device__ __forceinline__ uint32_t bfp(float x, float y) {
    __nv_bfloat162 t;
    t.x = __float2bfloat16_rn(x); t.y = __float2bfloat16_rn(y);
    return *reinterpret_cast<uint32_t*>(&t);
}
__device__ __forceinline__ void split2(float2 v, uint32_t& hi, uint32_t& lo) {
    const float hx = __bfloat162float(__float2bfloat16_rn(v.x));
    const float hy = __bfloat162float(__float2bfloat16_rn(v.y));
    hi = bfp(v.x, v.y);
    lo = bfp(v.x - hx, v.y - hy);
}
// fast tanh: (e^{2x}-1)/(e^{2x}+1), clamped; MUFU-based, branch-free.
// abs err ~1e-7 vs libm -- same order as the bf16-residual noise floor.
__device__ __forceinline__ float ftanh(float x) {
    const float xc = fminf(fmaxf(x, -9.0f), 9.0f);
    const float e  = __expf(2.0f * xc);
    return __fdividef(e - 1.0f, e + 1.0f);
}
// 16-byte async copy: global -> shared (producer == consumer thread)
__device__ __forceinline__ void cpa16(uint32_t saddr, const void* gptr) {
    asm volatile("cp.async.cg.shared.global [%0], [%1], 16;"
                 :: "r"(saddr), "l"(gptr) : "memory");
}
#define CPA_COMMIT() asm volatile("cp.async.commit_group;" ::: "memory")
#define CPA_WAIT(n)  asm volatile("cp.async.wait_group %0;" :: "n"(n) : "memory")

// ---------------------------------------------------------------------------
// Prep: pack W [N x kdim] fp32 into bf16 hi/lo B-fragments.
// Frag layout [c][j][l]: n = j*8 + l/4, k0 = c*16 + (l%4)*2;
// uint4 = {hi(k0),hi(k0+8),lo(k0),lo(k0+8)}
// ---------------------------------------------------------------------------
__global__ void __launch_bounds__(256)
prep_frag(const float* __restrict__ W, uint4* __restrict__ outF,
          int njt, int kdim)
{
    const int idx = blockIdx.x * 256 + threadIdx.x;
    const int l = idx & 31, g = idx >> 5;
    const int j = g % njt, c = g / njt;
    const int n  = j * 8 + (l >> 2);
    const int k0 = c * 16 + (l & 3) * 2;
    uint4 v;
    split2(*reinterpret_cast<const float2*>(&W[(size_t)n*kdim + k0]),     v.x, v.z);
    split2(*reinterpret_cast<const float2*>(&W[(size_t)n*kdim + k0 + 8]), v.y, v.w);
    outF[(c * njt + j) * 32 + l] = v;
}

// ---------------------------------------------------------------------------
// Persistent tensor-core Elman recurrence. 128 CTAs x 512 thr (16 warps),
// M=64 rows/CTA. A = h in SMEM bf16 hi/lo images (APAD=264 elem stride).
// B via per-warp cp.async ring (4 slots, 3-chunk lookahead, rolls across
// steps). i2h for step t is prefetched into REGISTERS before the mainloop
// so the epilogue's tanh inputs are latency-free. Fast MUFU tanh.
// ---------------------------------------------------------------------------
#define APAD 264
#define SM_ALO (64*APAD)
#define SM_BST (2*64*APAD*2)                  // byte offset of B ring (67,584)
#define BWARP_BYTES (4*4*32*16)               // 8192 B per warp
#define RNN_SMEM (SM_BST + 16*BWARP_BYTES)    // 198,656 B

__global__ void __launch_bounds__(512)
rnn_mma(const float* __restrict__ hc1, const uint4* __restrict__ Wfrag,
        const float* __restrict__ bias, const float* __restrict__ i2h,
        float* __restrict__ h2h_seq,
        uint32_t* __restrict__ hsHi, uint32_t* __restrict__ hsLo,
        float* __restrict__ hc1_out)
{
    extern __shared__ char sm8[];
    __nv_bfloat16* Ahi = (__nv_bfloat16*)sm8;
    __nv_bfloat16* Alo = Ahi + SM_ALO;

    const int tid = threadIdx.x;
    const int l   = tid & 31;
    const int wid = tid >> 5;
    const int wm  = wid & 1;
    const int wn  = wid >> 1;
    const int bm  = blockIdx.x * 64;

    // prologue: split hc1 rows into Ahi/Alo
    for (int i = tid; i < 64 * 128; i += 512) {
        const int m = i >> 7, kp = (i & 127) * 2;
        uint32_t hi, lo;
        split2(*reinterpret_cast<const float2*>(&hc1[(size_t)(bm+m)*HID + kp]), hi, lo);
        *reinterpret_cast<uint32_t*>(&Ahi[m*APAD + kp]) = hi;
        *reinterpret_cast<uint32_t*>(&Alo[m*APAD + kp]) = lo;
    }

    float2 bias2[4];
#pragma unroll
    for (int nt = 0; nt < 4; nt++)
        bias2[nt] = *reinterpret_cast<const float2*>(&bias[wn*32 + nt*8 + (l&3)*2]);

    const uint32_t aHiBase = smem_u32(Ahi);
    const uint32_t aLoBase = smem_u32(Alo);
    const int mi = l >> 3, rr8 = l & 7;
    const uint32_t ldsmOff = (uint32_t)((((mi & 1) * 8 + rr8) * APAD + (mi >> 1) * 8) * 2);

    // B ring: per-warp region; lane-private 16B cells
    const uint4* wbase = Wfrag + (wn * 4) * 32 + l;
    uint4* BwBase = (uint4*)(sm8 + SM_BST) + wid * 512;
    const uint32_t bStLane = smem_u32(BwBase) + (uint32_t)l * 16;

#pragma unroll
    for (int p = 0; p < 3; p++) {
#pragma unroll
        for (int nt = 0; nt < 4; nt++)
            cpa16(bStLane + (uint32_t)(p*2048 + nt*512), wbase + p*1024 + nt*32);
        CPA_COMMIT();
    }

    // per-thread output coordinates (16 elements: mt x nt x rr)
    // element (mt,nt,rr): row = wm*32+mt*16+(l>>2)+rr*8, col = wn*32+nt*8+(l&3)*2
    __syncthreads();

#pragma unroll 1
    for (int t = 0; t < T_STEPS; t++) {
        // ---- prefetch i2h for this step into registers (hidden by mainloop)
        float2 xi[2][4][2];
        {
            const size_t tb = (size_t)t * BATCH + bm;
#pragma unroll
            for (int mt = 0; mt < 2; mt++) {
#pragma unroll
                for (int rr = 0; rr < 2; rr++) {
                    const int mrel = wm*32 + mt*16 + (l >> 2) + rr*8;
                    const float* rowp = i2h + (tb + mrel) * HID + wn*32 + (l & 3)*2;
#pragma unroll
                    for (int nt = 0; nt < 4; nt++)
                        xi[mt][nt][rr] = *reinterpret_cast<const float2*>(rowp + nt*8);
                }
            }
        }

        float acc[2][4][4];
#pragma unroll
        for (int a = 0; a < 2; a++)
#pragma unroll
            for (int b = 0; b < 4; b++)
#pragma unroll
                for (int d = 0; d < 4; d++) acc[a][b][d] = 0.0f;

#pragma unroll 1
        for (int c = 0; c < 16; c++) {
            {
                const int cn = (c + 3) & 15;
                const int sl = (c + 3) & 3;
#pragma unroll
                for (int nt = 0; nt < 4; nt++)
                    cpa16(bStLane + (uint32_t)(sl*2048 + nt*512),
                          wbase + cn*1024 + nt*32);
                CPA_COMMIT();
            }
            CPA_WAIT(3);

            const uint4* slot = BwBase + (c & 3) * 128 + l;
            uint4 bcur[4];
#pragma unroll
            for (int nt = 0; nt < 4; nt++) bcur[nt] = slot[nt*32];

            uint32_t ah[2][4], al[2][4];
#pragma unroll
            for (int mt = 0; mt < 2; mt++) {
                const uint32_t rowByte = (uint32_t)(((wm*32 + mt*16) * APAD + c*16) * 2);
                ldsm4(ah[mt], aHiBase + rowByte + ldsmOff);
                ldsm4(al[mt], aLoBase + rowByte + ldsmOff);
            }
#pragma unroll
            for (int nt = 0; nt < 4; nt++) {
#pragma unroll
                for (int mt = 0; mt < 2; mt++) {
                    mma16816(acc[mt][nt], ah[mt], bcur[nt].x, bcur[nt].y);
                    mma16816(acc[mt][nt], ah[mt], bcur[nt].z, bcur[nt].w);
                    mma16816(acc[mt][nt], al[mt], bcur[nt].x, bcur[nt].y);
                }
            }
        }
        __syncthreads();   // all A reads of this step done

        // epilogue (i2h already in registers, fast tanh)
#pragma unroll
        for (int mt = 0; mt < 2; mt++) {
            const int m0 = wm*32 + mt*16 + (l >> 2);
#pragma unroll
            for (int nt = 0; nt < 4; nt++) {
                const int n = wn*32 + nt*8 + (l & 3)*2;
                const float2 bv = bias2[nt];
#pragma unroll
                for (int rr = 0; rr < 2; rr++) {
                    const int mrel = m0 + rr*8;
                    const float vx = acc[mt][nt][rr*2+0] + bv.x;
                    const float vy = acc[mt][nt][rr*2+1] + bv.y;
                    const size_t gi = ((size_t)t*BATCH + bm + mrel)*HID + n;
                    *reinterpret_cast<float2*>(&h2h_seq[gi]) = make_float2(vx, vy);
                    const float2 x2 = xi[mt][nt][rr];
                    const float h0 = ftanh(x2.x + vx);
                    const float h1 = ftanh(x2.y + vy);
                    uint32_t phi, plo;
                    split2(make_float2(h0, h1), phi, plo);
                    hsHi[gi >> 1] = phi;
                    hsLo[gi >> 1] = plo;
                    if (t == T_STEPS - 1)
                        *reinterpret_cast<float2*>(&hc1_out[(size_t)(bm+mrel)*HID + n])
                            = make_float2(h0, h1);
                    *reinterpret_cast<uint32_t*>(&Ahi[mrel*APAD + n]) = phi;
                    *reinterpret_cast<uint32_t*>(&Alo[mrel*APAD + n]) = plo;
                }
            }
        }
        __syncthreads();   // A updated before next step's ldmatrix
    }
}

// ---------------------------------------------------------------------------
// h2o + fcc fused HMMA kernel: out8 = tanh(hs @ W_h2o^T + b_h2o) @ W_fcc^T + b_fcc
// ---------------------------------------------------------------------------
__global__ void __launch_bounds__(256)
h2o_mma(const uint32_t* __restrict__ Hhi, const uint32_t* __restrict__ Hlo,
        const uint4* __restrict__ WfragO, const float* __restrict__ bias,
        const float* __restrict__ Wfcc, const float* __restrict__ bfcc,
        float* __restrict__ out8)
{
    __shared__ float Ws[NCLS * OUT_F];
    __shared__ float bs[NCLS];

    const int tid = threadIdx.x;
    const int l   = tid & 31;
    const int wid = tid >> 5;
    const int bm  = blockIdx.x * 128;

    for (int i = tid; i < NCLS * OUT_F; i += 256) Ws[i] = Wfcc[i];
    if (tid < NCLS) bs[tid] = bfcc[tid];

    float acc[8][4];
#pragma unroll
    for (int b = 0; b < 8; b++)
#pragma unroll
        for (int d = 0; d < 4; d++) acc[b][d] = 0.0f;

    const int row0 = bm + wid*16 + (l >> 2);
    const size_t r0b = (size_t)row0 * (HID/2);
    const size_t r1b = r0b + 8 * (HID/2);
    const int kb = (l & 3);
    const uint4* wb = WfragO + l;

#pragma unroll 1
    for (int c = 0; c < 16; c++) {
        uint32_t ah[4], al[4];
        const int base = c*8 + kb;
        ah[0] = Hhi[r0b + base];   ah[1] = Hhi[r1b + base];
        ah[2] = Hhi[r0b + base+4]; ah[3] = Hhi[r1b + base+4];
        al[0] = Hlo[r0b + base];   al[1] = Hlo[r1b + base];
        al[2] = Hlo[r0b + base+4]; al[3] = Hlo[r1b + base+4];
#pragma unroll
        for (int nt = 0; nt < 8; nt++) {
            const uint4 b = wb[(c*8 + nt)*32];
            mma16816(acc[nt], ah, b.x, b.y);
            mma16816(acc[nt], ah, b.z, b.w);
            mma16816(acc[nt], al, b.x, b.y);
        }
    }
    __syncthreads();   // Ws/bs visible

    float v[2][8][2];
#pragma unroll
    for (int nt = 0; nt < 8; nt++) {
        const int n = nt*8 + (l & 3)*2;
        const float2 bv = *reinterpret_cast<const float2*>(&bias[n]);
#pragma unroll
        for (int rr = 0; rr < 2; rr++) {
            v[rr][nt][0] = ftanh(acc[nt][rr*2+0] + bv.x);
            v[rr][nt][1] = ftanh(acc[nt][rr*2+1] + bv.y);
        }
    }

    const float2* Ws2 = reinterpret_cast<const float2*>(Ws);
    float p0[NCLS], p1[NCLS];
#pragma unroll
    for (int cls = 0; cls < NCLS; cls++) {
        float a0 = 0.0f, a1 = 0.0f;
#pragma unroll
        for (int nt = 0; nt < 8; nt++) {
            const float2 w = Ws2[cls*32 + nt*4 + (l & 3)];
            a0 += v[0][nt][0]*w.x + v[0][nt][1]*w.y;
            a1 += v[1][nt][0]*w.x + v[1][nt][1]*w.y;
        }
        a0 += __shfl_xor_sync(0xffffffffu, a0, 1);
        a0 += __shfl_xor_sync(0xffffffffu, a0, 2);
        a1 += __shfl_xor_sync(0xffffffffu, a1, 1);
        a1 += __shfl_xor_sync(0xffffffffu, a1, 2);
        p0[cls] = a0 + bs[cls];
        p1[cls] = a1 + bs[cls];
    }
    if ((l & 3) == 0) {
        const size_t r0 = (size_t)row0 * NCLS;
        const size_t r1 = (size_t)(row0 + 8) * NCLS;
        *reinterpret_cast<float4*>(&out8[r0])     = make_float4(p0[0], p0[1], p0[2], p0[3]);
        *reinterpret_cast<float4*>(&out8[r0 + 4]) = make_float4(p0[4], p0[5], p0[6], p0[7]);
        *reinterpret_cast<float4*>(&out8[r1])     = make_float4(p1[0], p1[1], p1[2], p1[3]);
        *reinterpret_cast<float4*>(&out8[r1 + 4]) = make_float4(p1[4], p1[5], p1[6], p1[7]);
    }
}

// ---------------------------------------------------------------------------
// i2h HMMA kernel: i2h = x @ W_i2h^T + b.
// ---------------------------------------------------------------------------
__global__ void __launch_bounds__(512)
i2h_mma(const float* __restrict__ x, const uint4* __restrict__ WfragI,
        const float* __restrict__ bias, float* __restrict__ C)
{
    const int tid = threadIdx.x;
    const int l   = tid & 31;
    const int wid = tid >> 5;
    const int wm  = wid & 3;
    const int wn  = wid >> 2;
    const int bm  = blockIdx.x * 128;

    float2 bias2[8];
#pragma unroll
    for (int nt = 0; nt < 8; nt++)
        bias2[nt] = *reinterpret_cast<const float2*>(&bias[wn*64 + nt*8 + (l&3)*2]);

    float acc[2][8][4];
#pragma unroll
    for (int a = 0; a < 2; a++)
#pragma unroll
        for (int b = 0; b < 8; b++)
#pragma unroll
            for (int d = 0; d < 4; d++) acc[a][b][d] = 0.0f;

#pragma unroll
    for (int c = 0; c < 4; c++) {
        uint32_t ah[2][4], al[2][4];
        const int k0 = c*16 + (l & 3)*2;
#pragma unroll
        for (int mt = 0; mt < 2; mt++) {
            const int r = bm + wm*32 + mt*16 + (l >> 2);
            const float* xr = x + (size_t)r * IN_F;
            split2(*reinterpret_cast<const float2*>(xr + k0),            ah[mt][0], al[mt][0]);
            split2(*reinterpret_cast<const float2*>(xr + 8*IN_F + k0),   ah[mt][1], al[mt][1]);
            split2(*reinterpret_cast<const float2*>(xr + k0 + 8),        ah[mt][2], al[mt][2]);
            split2(*reinterpret_cast<const float2*>(xr + 8*IN_F + k0+8), ah[mt][3], al[mt][3]);
        }
#pragma unroll
        for (int nt = 0; nt < 8; nt++) {
            const uint4 b = WfragI[((c*32) + wn*8 + nt)*32 + l];
#pragma unroll
            for (int mt = 0; mt < 2; mt++) {
                mma16816(acc[mt][nt], ah[mt], b.x, b.y);
                mma16816(acc[mt][nt], ah[mt], b.z, b.w);
                mma16816(acc[mt][nt], al[mt], b.x, b.y);
            }
        }
    }

#pragma unroll
    for (int mt = 0; mt < 2; mt++) {
        const int m0 = bm + wm*32 + mt*16 + (l >> 2);
#pragma unroll
        for (int nt = 0; nt < 8; nt++) {
            const int n = wn*64 + nt*8 + (l & 3)*2;
            const float2 bv = bias2[nt];
#pragma unroll
            for (int rr = 0; rr < 2; rr++) {
                const size_t gi = (size_t)(m0 + rr*8) * HID + n;
                *reinterpret_cast<float2*>(&C[gi]) =
                    make_float2(acc[mt][nt][rr*2+0] + bv.x,
                                acc[mt][nt][rr*2+1] + bv.y);
            }
        }
    }
}

// ---------------------------------------------------------------------------
__global__ void __launch_bounds__(256)
copy3_kernel(const float4* __restrict__ a, const float4* __restrict__ b,
             const float4* __restrict__ c,
             float4* __restrict__ oa, float4* __restrict__ ob,
             float4* __restrict__ oc)
{
    const size_t i = (size_t)blockIdx.x * blockDim.x + threadIdx.x;
    oa[i] = a[i]; ob[i] = b[i]; oc[i] = c[i];
}

// ---------------------------------------------------------------------------
extern "C" void kernel_launch(void* const* d_in, const int* in_sizes, int n_in,
                              void* d_out, int out_size)
{
    const float* x      = (const float*)d_in[0];
    const float* hc1    = (const float*)d_in[2];
    const float* hc2    = (const float*)d_in[3];
    const float* hc3    = (const float*)d_in[4];
    const float* hc4    = (const float*)d_in[5];
    const float* W_i2h  = (const float*)d_in[6];
    const float* b_i2h  = (const float*)d_in[7];
    const float* W_h2h  = (const float*)d_in[8];
    const float* b_h2h  = (const float*)d_in[9];
    const float* W_h2o  = (const float*)d_in[10];
    const float* b_h2o  = (const float*)d_in[11];
    const float* W_fcc  = (const float*)d_in[12];
    const float* b_fcc  = (const float*)d_in[13];
    float* out = (float*)d_out;

    uint32_t *hsHi, *hsLo; uint4 *wfrag, *wfragO, *wfragI;
    cudaGetSymbolAddress((void**)&hsHi,   g_hsHi);
    cudaGetSymbolAddress((void**)&hsLo,   g_hsLo);
    cudaGetSymbolAddress((void**)&wfrag,  g_wfrag);
    cudaGetSymbolAddress((void**)&wfragO, g_wfragO);
    cudaGetSymbolAddress((void**)&wfragI, g_wfragI);

    // pass-throughs + weight fragment prep
    copy3_kernel<<<(BH/4)/256, 256>>>(
        (const float4*)hc2, (const float4*)hc3, (const float4*)hc4,
        (float4*)(out + OFF_HC2), (float4*)(out + OFF_HC3), (float4*)(out + OFF_HC4));
    prep_frag<<<64, 256>>>(W_h2h, wfrag, 32, 256);
    prep_frag<<<16, 256>>>(W_h2o, wfragO, 8, 256);
    prep_frag<<<16, 256>>>(W_i2h, wfragI, 32, 64);

    // i2h_seq = x @ W_i2h^T + b  via HMMA
    i2h_mma<<<MROWS/128, 512>>>(x, wfragI, b_i2h, out + OFF_I2H);

    // persistent tensor-core 16-step recurrence
    cudaFuncSetAttribute(rnn_mma,
                         cudaFuncAttributeMaxDynamicSharedMemorySize, RNN_SMEM);
    rnn_mma<<<BATCH/64, 512, RNN_SMEM>>>(
        hc1, wfrag, b_h2h, out + OFF_I2H,
        out + OFF_H2H, hsHi, hsLo, out + OFF_HC1);

    // output_seq = fcc(tanh(hs @ W_h2o^T + b))  -- h2o + fcc fused
    h2o_mma<<<MROWS/128, 256>>>(hsHi, hsLo, wfragO, b_h2o,
                                W_fcc, b_fcc, out + OFF_OUTSEQ);
}